// round 9
// baseline (speedup 1.0000x reference)
#include <cuda_runtime.h>
#include <cuda_fp16.h>
#include <math.h>
#include <stdint.h>

#define NMAX 500000
#define NGROUPS 8
#define KT 27

// ---------------------------------------------------------------------------
// Device global scratch (no allocation allowed in kernel_launch)
// ---------------------------------------------------------------------------
__device__ __half g_xf16[(size_t)NMAX * 32];    // activations conv1, fp16 rows 64B
__device__ __half g_h1f16[(size_t)NMAX * 64];   // conv1 output (post-SiLU), rows 128B
__device__ __half g_w1[KT * 64 * 32];           // [k][n][c]
__device__ __half g_w2[KT * 64 * 64];           // [k][n][c]
__device__ int g_nbrt[(size_t)KT * NMAX];       // transposed neighbor idx [k][v]
__device__ float g_bias1[64];
__device__ float g_bias2[64];
__device__ float g_stats[16];
__device__ float g_scale[64];
__device__ float g_bias[64];

// ---------------------------------------------------------------------------
// Helpers
// ---------------------------------------------------------------------------
__device__ __forceinline__ uint32_t smem_to_u32(const void* p) {
    uint32_t a;
    asm("{ .reg .u64 t; cvta.to.shared.u64 t, %1; cvt.u32.u64 %0, t; }" : "=r"(a) : "l"(p));
    return a;
}
__device__ __forceinline__ void cp16(uint32_t dst, const void* src) {
    asm volatile("cp.async.cg.shared.global [%0], [%1], 16;" :: "r"(dst), "l"(src));
}
#define CP_COMMIT() asm volatile("cp.async.commit_group;" ::: "memory")
#define CP_WAIT(N) asm volatile("cp.async.wait_group %0;" :: "n"(N) : "memory")

__device__ __forceinline__ void ldsm4(uint32_t* r, uint32_t addr) {
    asm volatile("ldmatrix.sync.aligned.m8n8.x4.shared.b16 {%0,%1,%2,%3}, [%4];"
                 : "=r"(r[0]), "=r"(r[1]), "=r"(r[2]), "=r"(r[3]) : "r"(addr));
}
__device__ __forceinline__ void ldsm2(uint32_t* r, uint32_t addr) {
    asm volatile("ldmatrix.sync.aligned.m8n8.x2.shared.b16 {%0,%1}, [%2];"
                 : "=r"(r[0]), "=r"(r[1]) : "r"(addr));
}
__device__ __forceinline__ void mma16816(float* d, const uint32_t* a, const uint32_t* b) {
    asm volatile(
        "mma.sync.aligned.m16n8k16.row.col.f32.f16.f16.f32 "
        "{%0,%1,%2,%3}, {%4,%5,%6,%7}, {%8,%9}, {%0,%1,%2,%3};"
        : "+f"(d[0]), "+f"(d[1]), "+f"(d[2]), "+f"(d[3])
        : "r"(a[0]), "r"(a[1]), "r"(a[2]), "r"(a[3]), "r"(b[0]), "r"(b[1]));
}
__device__ __forceinline__ float silu_f(float t) { return t / (1.f + __expf(-t)); }

// ---------------------------------------------------------------------------
// Zero kernels
// ---------------------------------------------------------------------------
__global__ void zero_all_kernel() {
    if (threadIdx.x < 16) g_stats[threadIdx.x] = 0.f;
    if (threadIdx.x >= 16 && threadIdx.x < 80) g_bias1[threadIdx.x - 16] = 0.f;
    if (threadIdx.x >= 80 && threadIdx.x < 144) g_bias2[threadIdx.x - 80] = 0.f;
}
__global__ void zero_stats_kernel() {
    if (threadIdx.x < 16) g_stats[threadIdx.x] = 0.f;
}

// ---------------------------------------------------------------------------
// Fused: GN1 stats + fp32->fp16 conversion of x (single read pass)
// 4 threads per row; thread's quarter = channels q*8..q*8+7 = groups 2q, 2q+1
// ---------------------------------------------------------------------------
__global__ void gn1_prep_kernel(const float* __restrict__ x, int n) {
    int tid = blockIdx.x * blockDim.x + threadIdx.x;
    int total = gridDim.x * blockDim.x;     // multiple of 4
    int q = tid & 3;
    float s0 = 0.f, ss0 = 0.f, s1 = 0.f, ss1 = 0.f;
    long nQ = (long)n * 4;
    for (long e = tid; e < nQ; e += total) {
        long v = e >> 2;
        const float4* src = (const float4*)(x + v * 32 + q * 8);
        float4 a = src[0], b = src[1];
        uint32_t w[4];
        __half2 h;
        h = __floats2half2_rn(a.x, a.y); w[0] = *(uint32_t*)&h;
        h = __floats2half2_rn(a.z, a.w); w[1] = *(uint32_t*)&h;
        h = __floats2half2_rn(b.x, b.y); w[2] = *(uint32_t*)&h;
        h = __floats2half2_rn(b.z, b.w); w[3] = *(uint32_t*)&h;
        *(uint4*)(g_xf16 + v * 32 + q * 8) = *(uint4*)w;
        s0 += (a.x + a.y) + (a.z + a.w);
        ss0 += a.x * a.x + a.y * a.y + a.z * a.z + a.w * a.w;
        s1 += (b.x + b.y) + (b.z + b.w);
        ss1 += b.x * b.x + b.y * b.y + b.z * b.z + b.w * b.w;
    }
    __shared__ float sh[16];
    if (threadIdx.x < 16) sh[threadIdx.x] = 0.f;
    __syncthreads();
    atomicAdd(&sh[4 * q + 0], s0);
    atomicAdd(&sh[4 * q + 1], ss0);
    atomicAdd(&sh[4 * q + 2], s1);
    atomicAdd(&sh[4 * q + 3], ss1);
    __syncthreads();
    if (threadIdx.x < 16) atomicAdd(&g_stats[threadIdx.x], sh[threadIdx.x]);
}

template <int C>
__global__ void gn_finalize_kernel(const float* __restrict__ gamma,
                                   const float* __restrict__ beta, int n) {
    int c = threadIdx.x;
    if (c < C) {
        int g = c / (C / NGROUPS);
        float cnt = (float)n * (C / NGROUPS);
        float mean = g_stats[2 * g] / cnt;
        float var = g_stats[2 * g + 1] / cnt - mean * mean;
        float sc = gamma[c] * rsqrtf(var + 1e-5f);
        g_scale[c] = sc;
        g_bias[c] = beta[c] - mean * sc;
    }
}

// ---------------------------------------------------------------------------
// Prep: transpose nbr [v][k] -> g_nbrt [k][v]
// ---------------------------------------------------------------------------
__global__ void prep_nbr_kernel(const int* __restrict__ nbr, int n) {
    int v = blockIdx.x * blockDim.x + threadIdx.x;
    if (v >= n) return;
#pragma unroll
    for (int k = 0; k < KT; ++k)
        g_nbrt[(size_t)k * n + v] = nbr[(size_t)v * KT + k];
}

// ---------------------------------------------------------------------------
// Weight prep: fold GN scale into W, fp16, transpose to [k][n][c]
// ---------------------------------------------------------------------------
__global__ void prepW1_kernel(const float* __restrict__ W1) {
    int k = blockIdx.x, nn = threadIdx.x;
    float bs = 0.f;
    for (int c = 0; c < 32; ++c) {
        float w = W1[((size_t)(k * 32 + c)) * 64 + nn];
        bs += g_bias[c] * w;
        g_w1[((size_t)(k * 64 + nn)) * 32 + c] = __float2half_rn(w * g_scale[c]);
    }
    atomicAdd(&g_bias1[nn], bs);
}

__global__ void prepW2_kernel(const float* __restrict__ W2) {
    int k = blockIdx.x, nn = threadIdx.x;
    float bs = 0.f;
    for (int c = 0; c < 64; ++c) {
        float w = W2[((size_t)(k * 64 + c)) * 64 + nn];
        bs += g_bias[c] * w;
        g_w2[((size_t)(k * 64 + nn)) * 64 + c] = __float2half_rn(w * g_scale[c]);
    }
    atomicAdd(&g_bias2[nn], bs);
}

// ---------------------------------------------------------------------------
// mma.sync gather-conv, fp16 x fp16, 3-stage single-sync pipeline.
// Warp tile m32 x n64 (B fragments reused 2x).
// CONV2=false: 256 voxels/CTA (8 warps), CIN=32, rows 64B; out fp16;
//              epilogue also accumulates GN2 group stats into g_stats.
// CONV2=true : 192 voxels/CTA (6 warps), CIN=64, rows 128B; out fp32 += skip.
// ---------------------------------------------------------------------------
template <bool CONV2>
__global__ void __launch_bounds__(CONV2 ? 192 : 256, 2)
mma_conv_kernel(const __half* __restrict__ Araw,
                const int* __restrict__ nbrt,   // [k][v]
                const __half* __restrict__ Bw,
                const float* __restrict__ biasv,
                void* __restrict__ outp, int n) {
    constexpr int TM = CONV2 ? 192 : 256;
    constexpr uint32_t A_BYTES = CONV2 ? (192u * 128u) : (256u * 64u);
    constexpr uint32_t B_BYTES = CONV2 ? 8192u : 4096u;    // 64 rows
    constexpr uint32_t STRIDE = A_BYTES + B_BYTES;

    extern __shared__ __align__(1024) char dsmem[];
    float* sbias = (float*)dsmem;
    float* shst = (float*)(dsmem + 512);     // conv1 GN2 stats staging (16 floats)
    const uint32_t base0 = smem_to_u32(dsmem + 1024);

    const int tid = threadIdx.x;
    const int w = tid >> 5;
    const int lane = tid & 31;
    const int v0 = blockIdx.x * TM;

    if (tid < 64) sbias[tid] = biasv[tid];
    if constexpr (!CONV2) {
        if (tid < 16) shst[tid] = 0.f;
    }

    // fragment address components
    const uint32_t asel = (uint32_t)(lane >> 4);        // k-chunk low/high 8
    const int brow = lane & 7;
    const uint32_t bsel = (uint32_t)((lane >> 3) & 1);
    const int arow0 = w * 32 + (lane & 15);             // slab 0 row; slab1 = +16

    float acc[2][8][4];
#pragma unroll
    for (int s = 0; s < 2; ++s)
#pragma unroll
        for (int i = 0; i < 8; ++i)
#pragma unroll
            for (int j = 0; j < 4; ++j) acc[s][i][j] = 0.f;

    // stage loader: consecutive lanes cover one row's 16B chunks
    auto load_tap = [&](int k, uint32_t stage) {
        const int* nt = nbrt + (size_t)k * n;
        if constexpr (CONV2) {
            const int lrow = tid >> 3, lchk = tid & 7;   // 24 rows/pass, 8 passes
#pragma unroll
            for (int p = 0; p < 8; ++p) {
                int row = p * 24 + lrow;
                int vg = v0 + row;
                if (vg >= n) vg = n - 1;
                int idx = __ldg(&nt[vg]);
                cp16(stage + (uint32_t)row * 128 +
                         (((uint32_t)lchk ^ ((uint32_t)row & 7)) << 4),
                     (const char*)Araw + (size_t)idx * 128 + lchk * 16);
            }
#pragma unroll
            for (int j = 0; j < 3; ++j) {
                int q = tid + j * 192;               // 512 chunks of 16B
                if (q < 512) {
                    int row = q >> 3;
                    uint32_t c = (uint32_t)(q & 7);
                    cp16(stage + A_BYTES + (uint32_t)row * 128 +
                             ((c ^ ((uint32_t)row & 7)) << 4),
                         (const char*)Bw + (size_t)k * 8192 + (size_t)q * 16);
                }
            }
        } else {
            const int lrow = tid >> 2, lchk = tid & 3;   // 64 rows/pass, 4 passes
#pragma unroll
            for (int p = 0; p < 4; ++p) {
                int row = p * 64 + lrow;
                int vg = v0 + row;
                if (vg >= n) vg = n - 1;
                int idx = __ldg(&nt[vg]);
                cp16(stage + (uint32_t)row * 64 +
                         (((uint32_t)lchk ^ ((uint32_t)row & 3)) << 4),
                     (const char*)Araw + (size_t)idx * 64 + lchk * 16);
            }
            {
                int q = tid;                          // 256 chunks of 16B
                int row = q >> 2;
                uint32_t c = (uint32_t)(q & 3);
                cp16(stage + A_BYTES + (uint32_t)row * 64 +
                         ((c ^ ((uint32_t)row & 3)) << 4),
                     (const char*)Bw + (size_t)k * 4096 + (size_t)q * 16);
            }
        }
    };

    // prologue
    load_tap(0, base0);
    CP_COMMIT();

    for (int k = 0; k < KT; ++k) {
        // 3-stage, single sync: load (k+1)%3 never collides with (k-1)%3
        if (k + 1 < KT) {
            load_tap(k + 1, base0 + (uint32_t)((k + 1) % 3) * STRIDE);
            CP_COMMIT();
            CP_WAIT(1);
        } else {
            CP_WAIT(0);
        }
        __syncthreads();
        const uint32_t Ab = base0 + (uint32_t)(k % 3) * STRIDE;
        const uint32_t Bb = Ab + A_BYTES;
        if constexpr (CONV2) {
            uint32_t a[2][4][4];
#pragma unroll
            for (int s = 0; s < 2; ++s) {
                const int ar = arow0 + s * 16;
#pragma unroll
                for (int kc = 0; kc < 4; ++kc)
                    ldsm4(a[s][kc], Ab + (uint32_t)ar * 128 +
                                    ((((uint32_t)kc * 2 + asel) ^ ((uint32_t)ar & 7)) << 4));
            }
#pragma unroll
            for (int nt = 0; nt < 8; ++nt) {
#pragma unroll
                for (int kc = 0; kc < 4; ++kc) {
                    uint32_t b2[2];
                    ldsm2(b2, Bb + (uint32_t)nt * 1024 + (uint32_t)brow * 128 +
                                  ((((uint32_t)kc * 2 + bsel) ^ ((uint32_t)brow & 7)) << 4));
                    mma16816(acc[0][nt], a[0][kc], b2);
                    mma16816(acc[1][nt], a[1][kc], b2);
                }
            }
        } else {
            uint32_t a[2][2][4];
#pragma unroll
            for (int s = 0; s < 2; ++s) {
                const int ar = arow0 + s * 16;
#pragma unroll
                for (int kc = 0; kc < 2; ++kc)
                    ldsm4(a[s][kc], Ab + (uint32_t)ar * 64 +
                                    ((((uint32_t)kc * 2 + asel) ^ ((uint32_t)ar & 3)) << 4));
            }
#pragma unroll
            for (int nt = 0; nt < 8; ++nt) {
#pragma unroll
                for (int kc = 0; kc < 2; ++kc) {
                    uint32_t b2[2];
                    ldsm2(b2, Bb + (uint32_t)nt * 512 + (uint32_t)brow * 64 +
                                  ((((uint32_t)kc * 2 + bsel) ^ ((uint32_t)brow & 3)) << 4));
                    mma16816(acc[0][nt], a[0][kc], b2);
                    mma16816(acc[1][nt], a[1][kc], b2);
                }
            }
        }
    }

    // ---- epilogue ----
    const int g = lane >> 2, tg = lane & 3;
    float ls[8], lss[8];
    if constexpr (!CONV2) {
#pragma unroll
        for (int nt = 0; nt < 8; ++nt) { ls[nt] = 0.f; lss[nt] = 0.f; }
    }
#pragma unroll
    for (int s = 0; s < 2; ++s) {
        const int row0 = v0 + w * 32 + s * 16 + g;
#pragma unroll
        for (int half = 0; half < 2; ++half) {
            int v = row0 + half * 8;
            if (v < n) {
                if constexpr (CONV2) {
                    float* po = (float*)outp + (size_t)v * 64;
#pragma unroll
                    for (int nt = 0; nt < 8; ++nt) {
                        int c = nt * 8 + tg * 2;
                        float2 sk = *(float2*)(po + c);
                        float2 rr;
                        rr.x = silu_f(acc[s][nt][half * 2 + 0] + sbias[c]) + sk.x;
                        rr.y = silu_f(acc[s][nt][half * 2 + 1] + sbias[c + 1]) + sk.y;
                        *(float2*)(po + c) = rr;
                    }
                } else {
                    char* basep = (char*)outp + (size_t)v * 128;
#pragma unroll
                    for (int nt = 0; nt < 8; ++nt) {
                        int c = nt * 8 + tg * 2;
                        float f0 = silu_f(acc[s][nt][half * 2 + 0] + sbias[c]);
                        float f1 = silu_f(acc[s][nt][half * 2 + 1] + sbias[c + 1]);
                        __half2 hh = __floats2half2_rn(f0, f1);
                        *(uint32_t*)(basep + c * 2) = *(uint32_t*)&hh;
                        // GN2 stats: channels nt*8.. -> group nt
                        ls[nt] += f0 + f1;
                        lss[nt] += f0 * f0 + f1 * f1;
                    }
                }
            }
        }
    }
    if constexpr (!CONV2) {
        // warp-uniform shared addresses -> ptxas REDUX-aggregates
#pragma unroll
        for (int nt = 0; nt < 8; ++nt) {
            atomicAdd(&shst[2 * nt], ls[nt]);
            atomicAdd(&shst[2 * nt + 1], lss[nt]);
        }
        __syncthreads();
        if (tid < 16) atomicAdd(&g_stats[tid], shst[tid]);
    }
}

// ---------------------------------------------------------------------------
// Scalar skip conv (proven): out = x @ Wskip + bskip
// ---------------------------------------------------------------------------
__global__ void __launch_bounds__(256, 2)
skip_kernel(const float* __restrict__ xin,
            const float* __restrict__ W,       // [32][64]
            const float* __restrict__ obias,   // [64]
            float* __restrict__ out, int n) {
    constexpr int TM = 256;
    __shared__ __align__(16) float As[32][TM + 4];
    __shared__ __align__(16) float Bs[32][64];

    const int tid = threadIdx.x;
    const int v0 = blockIdx.x * TM;
    const int vv = tid >> 3;
    const int ov = tid & 7;
    const int c4 = (tid & 7) << 2;

    float acc[8][8];
#pragma unroll
    for (int i = 0; i < 8; ++i)
#pragma unroll
        for (int j = 0; j < 8; ++j) acc[i][j] = 0.f;

    {
        const float4* Wp = (const float4*)W;
        float4* Bp = (float4*)(&Bs[0][0]);
        Bp[tid] = Wp[tid];
        Bp[tid + 256] = Wp[tid + 256];
#pragma unroll
        for (int it = 0; it < 8; ++it) {
            int v = it * 32 + (tid >> 3);
            int j = v0 + v;
            if (j >= n) j = n - 1;
            float4 xv = *(const float4*)(xin + (long)j * 32 + c4);
            As[c4 + 0][v] = xv.x;
            As[c4 + 1][v] = xv.y;
            As[c4 + 2][v] = xv.z;
            As[c4 + 3][v] = xv.w;
        }
        __syncthreads();
#pragma unroll
        for (int c = 0; c < 32; ++c) {
            float a[8], b[8];
            *(float4*)&a[0] = *(const float4*)&As[c][vv * 8];
            *(float4*)&a[4] = *(const float4*)&As[c][vv * 8 + 4];
            *(float4*)&b[0] = *(const float4*)&Bs[c][ov * 4];
            *(float4*)&b[4] = *(const float4*)&Bs[c][32 + ov * 4];
#pragma unroll
            for (int i = 0; i < 8; ++i)
#pragma unroll
                for (int j = 0; j < 8; ++j)
                    acc[i][j] = fmaf(a[i], b[j], acc[i][j]);
        }
    }
    float ob[8];
#pragma unroll
    for (int j = 0; j < 4; ++j) {
        ob[j] = obias[ov * 4 + j];
        ob[4 + j] = obias[32 + ov * 4 + j];
    }
#pragma unroll
    for (int i = 0; i < 8; ++i) {
        int v = v0 + vv * 8 + i;
        if (v < n) {
            float* po = out + (long)v * 64 + ov * 4;
            *(float4*)po = make_float4(acc[i][0] + ob[0], acc[i][1] + ob[1],
                                       acc[i][2] + ob[2], acc[i][3] + ob[3]);
            *(float4*)(po + 32) = make_float4(acc[i][4] + ob[4], acc[i][5] + ob[5],
                                              acc[i][6] + ob[6], acc[i][7] + ob[7]);
        }
    }
}

__global__ void fill_tail_kernel(float* out, long start, long end) {
    long i = start + (long)blockIdx.x * blockDim.x + threadIdx.x;
    if (i < end) out[i] = 0.f;
}

// ---------------------------------------------------------------------------
extern "C" void kernel_launch(void* const* d_in, const int* in_sizes, int n_in,
                              void* d_out, int out_size) {
    const float* x      = (const float*)d_in[0];
    const int*   nbr    = (const int*)d_in[1];
    const float* gamma1 = (const float*)d_in[2];
    const float* beta1  = (const float*)d_in[3];
    const float* W1     = (const float*)d_in[4];
    const float* gamma2 = (const float*)d_in[5];
    const float* beta2  = (const float*)d_in[6];
    const float* W2     = (const float*)d_in[7];
    const float* Wskip  = (const float*)d_in[8];
    const float* bskip  = (const float*)d_in[9];
    float* out = (float*)d_out;

    int n = in_sizes[0] / 32;
    int nblk = (n + 255) / 256;
    int nblk1 = (n + 255) / 256;
    int nblk2 = (n + 191) / 192;

    __half *xf16p = nullptr, *h1p = nullptr, *w1p = nullptr, *w2p = nullptr;
    float *b1p = nullptr, *b2p = nullptr;
    int *nbrtp = nullptr;
    cudaGetSymbolAddress((void**)&xf16p, g_xf16);
    cudaGetSymbolAddress((void**)&h1p, g_h1f16);
    cudaGetSymbolAddress((void**)&w1p, g_w1);
    cudaGetSymbolAddress((void**)&w2p, g_w2);
    cudaGetSymbolAddress((void**)&b1p, g_bias1);
    cudaGetSymbolAddress((void**)&b2p, g_bias2);
    cudaGetSymbolAddress((void**)&nbrtp, g_nbrt);

    const int SMEM1 = 1024 + 3 * (16384 + 4096);      // 62464
    const int SMEM2 = 1024 + 3 * (24576 + 8192);      // 99328
    cudaFuncSetAttribute(mma_conv_kernel<false>,
                         cudaFuncAttributeMaxDynamicSharedMemorySize, SMEM1);
    cudaFuncSetAttribute(mma_conv_kernel<true>,
                         cudaFuncAttributeMaxDynamicSharedMemorySize, SMEM2);

    // skip path first (conv2 epilogue accumulates onto it)
    skip_kernel<<<nblk, 256>>>(x, Wskip, bskip, out, n);

    // nbr transpose + fused GN1 stats/x conversion
    prep_nbr_kernel<<<nblk, 256>>>(nbr, n);
    zero_all_kernel<<<1, 160>>>();
    gn1_prep_kernel<<<1184, 256>>>(x, n);
    gn_finalize_kernel<32><<<1, 64>>>(gamma1, beta1, n);
    prepW1_kernel<<<KT, 64>>>(W1);
    zero_stats_kernel<<<1, 16>>>();          // reset for GN2 accumulation

    // conv1 -> g_h1f16 (fp16, post-SiLU); also accumulates GN2 stats
    mma_conv_kernel<false><<<nblk1, 256, SMEM1>>>(
        xf16p, nbrtp, w1p, b1p, (void*)h1p, n);

    gn_finalize_kernel<64><<<1, 64>>>(gamma2, beta2, n);
    prepW2_kernel<<<KT, 64>>>(W2);

    // conv2 -> out (accumulates skip)
    mma_conv_kernel<true><<<nblk2, 192, SMEM2>>>(
        h1p, nbrtp, w2p, b2p, (void*)out, n);

    long main_elems = (long)n * 64;
    if ((long)out_size > main_elems) {
        long tail = (long)out_size - main_elems;
        int tb = (int)((tail + 255) / 256);
        fill_tail_kernel<<<tb, 256>>>(out, main_elems, (long)out_size);
    }
}

// round 10
// speedup vs baseline: 1.4865x; 1.4865x over previous
#include <cuda_runtime.h>
#include <cuda_fp16.h>
#include <math.h>
#include <stdint.h>

#define NMAX 500000
#define NGROUPS 8
#define KT 27

// ---------------------------------------------------------------------------
// Device global scratch (no allocation allowed in kernel_launch)
// ---------------------------------------------------------------------------
__device__ __half g_xf16[(size_t)NMAX * 32];    // activations conv1, fp16 rows 64B
__device__ __half g_h1f16[(size_t)NMAX * 64];   // conv1 output (post-SiLU), rows 128B
__device__ __half g_w1[KT * 64 * 32];           // [k][n][c]
__device__ __half g_w2[KT * 64 * 64];           // [k][n][c]
__device__ int g_nbrt[(size_t)KT * NMAX];       // transposed neighbor idx [k][v]
__device__ float g_bias1[64];
__device__ float g_bias2[64];
__device__ float g_stats[16];
__device__ float g_scale[64];
__device__ float g_bias[64];

// ---------------------------------------------------------------------------
// Helpers
// ---------------------------------------------------------------------------
__device__ __forceinline__ uint32_t smem_to_u32(const void* p) {
    uint32_t a;
    asm("{ .reg .u64 t; cvta.to.shared.u64 t, %1; cvt.u32.u64 %0, t; }" : "=r"(a) : "l"(p));
    return a;
}
__device__ __forceinline__ void cp16(uint32_t dst, const void* src) {
    asm volatile("cp.async.cg.shared.global [%0], [%1], 16;" :: "r"(dst), "l"(src));
}
#define CP_COMMIT() asm volatile("cp.async.commit_group;" ::: "memory")
#define CP_WAIT(N) asm volatile("cp.async.wait_group %0;" :: "n"(N) : "memory")

__device__ __forceinline__ void ldsm4(uint32_t* r, uint32_t addr) {
    asm volatile("ldmatrix.sync.aligned.m8n8.x4.shared.b16 {%0,%1,%2,%3}, [%4];"
                 : "=r"(r[0]), "=r"(r[1]), "=r"(r[2]), "=r"(r[3]) : "r"(addr));
}
__device__ __forceinline__ void ldsm2(uint32_t* r, uint32_t addr) {
    asm volatile("ldmatrix.sync.aligned.m8n8.x2.shared.b16 {%0,%1}, [%2];"
                 : "=r"(r[0]), "=r"(r[1]) : "r"(addr));
}
__device__ __forceinline__ void mma16816(float* d, const uint32_t* a, const uint32_t* b) {
    asm volatile(
        "mma.sync.aligned.m16n8k16.row.col.f32.f16.f16.f32 "
        "{%0,%1,%2,%3}, {%4,%5,%6,%7}, {%8,%9}, {%0,%1,%2,%3};"
        : "+f"(d[0]), "+f"(d[1]), "+f"(d[2]), "+f"(d[3])
        : "r"(a[0]), "r"(a[1]), "r"(a[2]), "r"(a[3]), "r"(b[0]), "r"(b[1]));
}
__device__ __forceinline__ float silu_f(float t) { return t / (1.f + __expf(-t)); }

// ---------------------------------------------------------------------------
// Zero kernels
// ---------------------------------------------------------------------------
__global__ void zero_all_kernel() {
    if (threadIdx.x < 16) g_stats[threadIdx.x] = 0.f;
    if (threadIdx.x >= 16 && threadIdx.x < 80) g_bias1[threadIdx.x - 16] = 0.f;
    if (threadIdx.x >= 80 && threadIdx.x < 144) g_bias2[threadIdx.x - 80] = 0.f;
}
__global__ void zero_stats_kernel() {
    if (threadIdx.x < 16) g_stats[threadIdx.x] = 0.f;
}

// ---------------------------------------------------------------------------
// Fused: GN1 stats + fp32->fp16 conversion of x (single read pass)
// 4 threads per row; thread's quarter = channels q*8..q*8+7 = groups 2q, 2q+1
// ---------------------------------------------------------------------------
__global__ void gn1_prep_kernel(const float* __restrict__ x, int n) {
    int tid = blockIdx.x * blockDim.x + threadIdx.x;
    int total = gridDim.x * blockDim.x;     // multiple of 4
    int q = tid & 3;
    float s0 = 0.f, ss0 = 0.f, s1 = 0.f, ss1 = 0.f;
    long nQ = (long)n * 4;
    for (long e = tid; e < nQ; e += total) {
        long v = e >> 2;
        const float4* src = (const float4*)(x + v * 32 + q * 8);
        float4 a = src[0], b = src[1];
        uint32_t w[4];
        __half2 h;
        h = __floats2half2_rn(a.x, a.y); w[0] = *(uint32_t*)&h;
        h = __floats2half2_rn(a.z, a.w); w[1] = *(uint32_t*)&h;
        h = __floats2half2_rn(b.x, b.y); w[2] = *(uint32_t*)&h;
        h = __floats2half2_rn(b.z, b.w); w[3] = *(uint32_t*)&h;
        *(uint4*)(g_xf16 + v * 32 + q * 8) = *(uint4*)w;
        s0 += (a.x + a.y) + (a.z + a.w);
        ss0 += a.x * a.x + a.y * a.y + a.z * a.z + a.w * a.w;
        s1 += (b.x + b.y) + (b.z + b.w);
        ss1 += b.x * b.x + b.y * b.y + b.z * b.z + b.w * b.w;
    }
    __shared__ float sh[16];
    if (threadIdx.x < 16) sh[threadIdx.x] = 0.f;
    __syncthreads();
    atomicAdd(&sh[4 * q + 0], s0);
    atomicAdd(&sh[4 * q + 1], ss0);
    atomicAdd(&sh[4 * q + 2], s1);
    atomicAdd(&sh[4 * q + 3], ss1);
    __syncthreads();
    if (threadIdx.x < 16) atomicAdd(&g_stats[threadIdx.x], sh[threadIdx.x]);
}

// GN stats over g_h1f16 (fp16 rows of 64 channels)
__global__ void gn_reduce_h1_kernel(int n) {
    int tid = blockIdx.x * blockDim.x + threadIdx.x;
    int total = gridDim.x * blockDim.x;
    int sub = tid & 7;                 // 8 channels per group
    float s = 0.f, ss = 0.f;
    for (long r = tid >> 3; r < n; r += (total >> 3)) {
        uint4 H = *(const uint4*)(g_h1f16 + (size_t)r * 64 + sub * 8);
        uint32_t hu[4] = {H.x, H.y, H.z, H.w};
#pragma unroll
        for (int j = 0; j < 4; ++j) {
            __half2 h2 = *reinterpret_cast<__half2*>(&hu[j]);
            float2 f = __half22float2(h2);
            s += f.x + f.y;
            ss += f.x * f.x + f.y * f.y;
        }
    }
    __shared__ float sh[16];
    if (threadIdx.x < 16) sh[threadIdx.x] = 0.f;
    __syncthreads();
    atomicAdd(&sh[2 * sub], s);
    atomicAdd(&sh[2 * sub + 1], ss);
    __syncthreads();
    if (threadIdx.x < 16) atomicAdd(&g_stats[threadIdx.x], sh[threadIdx.x]);
}

template <int C>
__global__ void gn_finalize_kernel(const float* __restrict__ gamma,
                                   const float* __restrict__ beta, int n) {
    int c = threadIdx.x;
    if (c < C) {
        int g = c / (C / NGROUPS);
        float cnt = (float)n * (C / NGROUPS);
        float mean = g_stats[2 * g] / cnt;
        float var = g_stats[2 * g + 1] / cnt - mean * mean;
        float sc = gamma[c] * rsqrtf(var + 1e-5f);
        g_scale[c] = sc;
        g_bias[c] = beta[c] - mean * sc;
    }
}

// ---------------------------------------------------------------------------
// Prep: transpose nbr [v][k] -> g_nbrt [k][v]
// ---------------------------------------------------------------------------
__global__ void prep_nbr_kernel(const int* __restrict__ nbr, int n) {
    int v = blockIdx.x * blockDim.x + threadIdx.x;
    if (v >= n) return;
#pragma unroll
    for (int k = 0; k < KT; ++k)
        g_nbrt[(size_t)k * n + v] = nbr[(size_t)v * KT + k];
}

// ---------------------------------------------------------------------------
// Weight prep: fold GN scale into W, fp16, transpose to [k][n][c]
// ---------------------------------------------------------------------------
__global__ void prepW1_kernel(const float* __restrict__ W1) {
    int k = blockIdx.x, nn = threadIdx.x;
    float bs = 0.f;
    for (int c = 0; c < 32; ++c) {
        float w = W1[((size_t)(k * 32 + c)) * 64 + nn];
        bs += g_bias[c] * w;
        g_w1[((size_t)(k * 64 + nn)) * 32 + c] = __float2half_rn(w * g_scale[c]);
    }
    atomicAdd(&g_bias1[nn], bs);
}

__global__ void prepW2_kernel(const float* __restrict__ W2) {
    int k = blockIdx.x, nn = threadIdx.x;
    float bs = 0.f;
    for (int c = 0; c < 64; ++c) {
        float w = W2[((size_t)(k * 64 + c)) * 64 + nn];
        bs += g_bias[c] * w;
        g_w2[((size_t)(k * 64 + nn)) * 64 + c] = __float2half_rn(w * g_scale[c]);
    }
    atomicAdd(&g_bias2[nn], bs);
}

// ---------------------------------------------------------------------------
// mma.sync gather-conv, fp16 x fp16 (proven R8 structure).
// One CTA = 256 voxels x 64 outputs, 8 warps, each warp m32 x n64.
// Gather: consecutive lanes cover one row's 16B chunks (coalesced).
// CONV2=false: CIN=32, rows 64B, 3-stage pipeline; out fp16.
// CONV2=true : CIN=64, rows 128B, 2-stage pipeline; out fp32 += skip.
// ---------------------------------------------------------------------------
template <bool CONV2>
__global__ void __launch_bounds__(256, 2)
mma_conv_kernel(const __half* __restrict__ Araw,
                const int* __restrict__ nbrt,   // [k][v]
                const __half* __restrict__ Bw,
                const float* __restrict__ biasv,
                void* __restrict__ outp, int n) {
    constexpr uint32_t A_BYTES = CONV2 ? 32768u : 16384u;  // 256 rows
    constexpr uint32_t B_BYTES = CONV2 ? 8192u : 4096u;    // 64 rows
    constexpr uint32_t STRIDE = A_BYTES + B_BYTES;
    constexpr int NSTAGE = CONV2 ? 2 : 3;

    extern __shared__ __align__(1024) char dsmem[];
    float* sbias = (float*)dsmem;
    const uint32_t base0 = smem_to_u32(dsmem + 1024);

    const int tid = threadIdx.x;
    const int w = tid >> 5;
    const int lane = tid & 31;
    const int v0 = blockIdx.x * 256;

    if (tid < 64) sbias[tid] = biasv[tid];

    // fragment address components
    const uint32_t asel = (uint32_t)(lane >> 4);        // k-chunk low/high 8
    const int brow = lane & 7;
    const uint32_t bsel = (uint32_t)((lane >> 3) & 1);
    const int arow0 = w * 32 + (lane & 15);             // slab 0 row; slab1 = +16

    float acc[2][8][4];
#pragma unroll
    for (int s = 0; s < 2; ++s)
#pragma unroll
        for (int i = 0; i < 8; ++i)
#pragma unroll
            for (int j = 0; j < 4; ++j) acc[s][i][j] = 0.f;

    // stage loader: consecutive lanes cover one row's 16B chunks
    auto load_tap = [&](int k, uint32_t stage) {
        const int* nt = nbrt + (size_t)k * n;
        if constexpr (CONV2) {
            const int lrow = tid >> 3, lchk = tid & 7;   // 32 rows/pass, 8 passes
#pragma unroll
            for (int p = 0; p < 8; ++p) {
                int row = p * 32 + lrow;
                int vg = v0 + row;
                if (vg >= n) vg = n - 1;
                int idx = __ldg(&nt[vg]);
                cp16(stage + (uint32_t)row * 128 +
                         (((uint32_t)lchk ^ ((uint32_t)row & 7)) << 4),
                     (const char*)Araw + (size_t)idx * 128 + lchk * 16);
            }
#pragma unroll
            for (int j = 0; j < 2; ++j) {
                int q = tid + j * 256;               // 512 chunks of 16B
                int row = q >> 3;
                uint32_t c = (uint32_t)(q & 7);
                cp16(stage + A_BYTES + (uint32_t)row * 128 +
                         ((c ^ ((uint32_t)row & 7)) << 4),
                     (const char*)Bw + (size_t)k * 8192 + (size_t)q * 16);
            }
        } else {
            const int lrow = tid >> 2, lchk = tid & 3;   // 64 rows/pass, 4 passes
#pragma unroll
            for (int p = 0; p < 4; ++p) {
                int row = p * 64 + lrow;
                int vg = v0 + row;
                if (vg >= n) vg = n - 1;
                int idx = __ldg(&nt[vg]);
                cp16(stage + (uint32_t)row * 64 +
                         (((uint32_t)lchk ^ ((uint32_t)row & 3)) << 4),
                     (const char*)Araw + (size_t)idx * 64 + lchk * 16);
            }
            {
                int q = tid;                          // 256 chunks of 16B
                int row = q >> 2;
                uint32_t c = (uint32_t)(q & 3);
                cp16(stage + A_BYTES + (uint32_t)row * 64 +
                         ((c ^ ((uint32_t)row & 3)) << 4),
                     (const char*)Bw + (size_t)k * 4096 + (size_t)q * 16);
            }
        }
    };

    // prologue
    load_tap(0, base0);
    CP_COMMIT();

    for (int k = 0; k < KT; ++k) {
        if constexpr (CONV2) {
            // 2-stage: top sync protects overwrite of stage holding tap k-1
            __syncthreads();
            if (k + 1 < KT) {
                load_tap(k + 1, base0 + (uint32_t)((k + 1) & 1) * STRIDE);
                CP_COMMIT();
                CP_WAIT(1);
            } else {
                CP_WAIT(0);
            }
            __syncthreads();
        } else {
            // 3-stage, single sync: load (k+1)%3 never collides with (k-1)%3
            if (k + 1 < KT) {
                load_tap(k + 1, base0 + (uint32_t)((k + 1) % 3) * STRIDE);
                CP_COMMIT();
                CP_WAIT(1);
            } else {
                CP_WAIT(0);
            }
            __syncthreads();
        }
        const uint32_t Ab = base0 + (uint32_t)(k % NSTAGE) * STRIDE;
        const uint32_t Bb = Ab + A_BYTES;
        if constexpr (CONV2) {
            uint32_t a[2][4][4];
#pragma unroll
            for (int s = 0; s < 2; ++s) {
                const int ar = arow0 + s * 16;
#pragma unroll
                for (int kc = 0; kc < 4; ++kc)
                    ldsm4(a[s][kc], Ab + (uint32_t)ar * 128 +
                                    ((((uint32_t)kc * 2 + asel) ^ ((uint32_t)ar & 7)) << 4));
            }
#pragma unroll
            for (int nt = 0; nt < 8; ++nt) {
#pragma unroll
                for (int kc = 0; kc < 4; ++kc) {
                    uint32_t b2[2];
                    ldsm2(b2, Bb + (uint32_t)nt * 1024 + (uint32_t)brow * 128 +
                                  ((((uint32_t)kc * 2 + bsel) ^ ((uint32_t)brow & 7)) << 4));
                    mma16816(acc[0][nt], a[0][kc], b2);
                    mma16816(acc[1][nt], a[1][kc], b2);
                }
            }
        } else {
            uint32_t a[2][2][4];
#pragma unroll
            for (int s = 0; s < 2; ++s) {
                const int ar = arow0 + s * 16;
#pragma unroll
                for (int kc = 0; kc < 2; ++kc)
                    ldsm4(a[s][kc], Ab + (uint32_t)ar * 64 +
                                    ((((uint32_t)kc * 2 + asel) ^ ((uint32_t)ar & 3)) << 4));
            }
#pragma unroll
            for (int nt = 0; nt < 8; ++nt) {
#pragma unroll
                for (int kc = 0; kc < 2; ++kc) {
                    uint32_t b2[2];
                    ldsm2(b2, Bb + (uint32_t)nt * 512 + (uint32_t)brow * 64 +
                                  ((((uint32_t)kc * 2 + bsel) ^ ((uint32_t)brow & 3)) << 4));
                    mma16816(acc[0][nt], a[0][kc], b2);
                    mma16816(acc[1][nt], a[1][kc], b2);
                }
            }
        }
    }

    // ---- epilogue ----
    const int g = lane >> 2, tg = lane & 3;
#pragma unroll
    for (int s = 0; s < 2; ++s) {
        const int row0 = v0 + w * 32 + s * 16 + g;
#pragma unroll
        for (int half = 0; half < 2; ++half) {
            int v = row0 + half * 8;
            if (v < n) {
                if constexpr (CONV2) {
                    float* po = (float*)outp + (size_t)v * 64;
#pragma unroll
                    for (int nt = 0; nt < 8; ++nt) {
                        int c = nt * 8 + tg * 2;
                        float2 sk = *(float2*)(po + c);
                        float2 rr;
                        rr.x = silu_f(acc[s][nt][half * 2 + 0] + sbias[c]) + sk.x;
                        rr.y = silu_f(acc[s][nt][half * 2 + 1] + sbias[c + 1]) + sk.y;
                        *(float2*)(po + c) = rr;
                    }
                } else {
                    char* basep = (char*)outp + (size_t)v * 128;
#pragma unroll
                    for (int nt = 0; nt < 8; ++nt) {
                        int c = nt * 8 + tg * 2;
                        float f0 = silu_f(acc[s][nt][half * 2 + 0] + sbias[c]);
                        float f1 = silu_f(acc[s][nt][half * 2 + 1] + sbias[c + 1]);
                        __half2 hh = __floats2half2_rn(f0, f1);
                        *(uint32_t*)(basep + c * 2) = *(uint32_t*)&hh;
                    }
                }
            }
        }
    }
}

// ---------------------------------------------------------------------------
// Scalar skip conv (proven): out = x @ Wskip + bskip
// ---------------------------------------------------------------------------
__global__ void __launch_bounds__(256, 2)
skip_kernel(const float* __restrict__ xin,
            const float* __restrict__ W,       // [32][64]
            const float* __restrict__ obias,   // [64]
            float* __restrict__ out, int n) {
    constexpr int TM = 256;
    __shared__ __align__(16) float As[32][TM + 4];
    __shared__ __align__(16) float Bs[32][64];

    const int tid = threadIdx.x;
    const int v0 = blockIdx.x * TM;
    const int vv = tid >> 3;
    const int ov = tid & 7;
    const int c4 = (tid & 7) << 2;

    float acc[8][8];
#pragma unroll
    for (int i = 0; i < 8; ++i)
#pragma unroll
        for (int j = 0; j < 8; ++j) acc[i][j] = 0.f;

    {
        const float4* Wp = (const float4*)W;
        float4* Bp = (float4*)(&Bs[0][0]);
        Bp[tid] = Wp[tid];
        Bp[tid + 256] = Wp[tid + 256];
#pragma unroll
        for (int it = 0; it < 8; ++it) {
            int v = it * 32 + (tid >> 3);
            int j = v0 + v;
            if (j >= n) j = n - 1;
            float4 xv = *(const float4*)(xin + (long)j * 32 + c4);
            As[c4 + 0][v] = xv.x;
            As[c4 + 1][v] = xv.y;
            As[c4 + 2][v] = xv.z;
            As[c4 + 3][v] = xv.w;
        }
        __syncthreads();
#pragma unroll
        for (int c = 0; c < 32; ++c) {
            float a[8], b[8];
            *(float4*)&a[0] = *(const float4*)&As[c][vv * 8];
            *(float4*)&a[4] = *(const float4*)&As[c][vv * 8 + 4];
            *(float4*)&b[0] = *(const float4*)&Bs[c][ov * 4];
            *(float4*)&b[4] = *(const float4*)&Bs[c][32 + ov * 4];
#pragma unroll
            for (int i = 0; i < 8; ++i)
#pragma unroll
                for (int j = 0; j < 8; ++j)
                    acc[i][j] = fmaf(a[i], b[j], acc[i][j]);
        }
    }
    float ob[8];
#pragma unroll
    for (int j = 0; j < 4; ++j) {
        ob[j] = obias[ov * 4 + j];
        ob[4 + j] = obias[32 + ov * 4 + j];
    }
#pragma unroll
    for (int i = 0; i < 8; ++i) {
        int v = v0 + vv * 8 + i;
        if (v < n) {
            float* po = out + (long)v * 64 + ov * 4;
            *(float4*)po = make_float4(acc[i][0] + ob[0], acc[i][1] + ob[1],
                                       acc[i][2] + ob[2], acc[i][3] + ob[3]);
            *(float4*)(po + 32) = make_float4(acc[i][4] + ob[4], acc[i][5] + ob[5],
                                              acc[i][6] + ob[6], acc[i][7] + ob[7]);
        }
    }
}

__global__ void fill_tail_kernel(float* out, long start, long end) {
    long i = start + (long)blockIdx.x * blockDim.x + threadIdx.x;
    if (i < end) out[i] = 0.f;
}

// ---------------------------------------------------------------------------
extern "C" void kernel_launch(void* const* d_in, const int* in_sizes, int n_in,
                              void* d_out, int out_size) {
    const float* x      = (const float*)d_in[0];
    const int*   nbr    = (const int*)d_in[1];
    const float* gamma1 = (const float*)d_in[2];
    const float* beta1  = (const float*)d_in[3];
    const float* W1     = (const float*)d_in[4];
    const float* gamma2 = (const float*)d_in[5];
    const float* beta2  = (const float*)d_in[6];
    const float* W2     = (const float*)d_in[7];
    const float* Wskip  = (const float*)d_in[8];
    const float* bskip  = (const float*)d_in[9];
    float* out = (float*)d_out;

    int n = in_sizes[0] / 32;
    int nblk = (n + 255) / 256;
    int nblk_mma = (n + 255) / 256;

    __half *xf16p = nullptr, *h1p = nullptr, *w1p = nullptr, *w2p = nullptr;
    float *b1p = nullptr, *b2p = nullptr;
    int *nbrtp = nullptr;
    cudaGetSymbolAddress((void**)&xf16p, g_xf16);
    cudaGetSymbolAddress((void**)&h1p, g_h1f16);
    cudaGetSymbolAddress((void**)&w1p, g_w1);
    cudaGetSymbolAddress((void**)&w2p, g_w2);
    cudaGetSymbolAddress((void**)&b1p, g_bias1);
    cudaGetSymbolAddress((void**)&b2p, g_bias2);
    cudaGetSymbolAddress((void**)&nbrtp, g_nbrt);

    const int SMEM1 = 1024 + 3 * (16384 + 4096);    // 62464
    const int SMEM2 = 1024 + 2 * (32768 + 8192);    // 82944
    cudaFuncSetAttribute(mma_conv_kernel<false>,
                         cudaFuncAttributeMaxDynamicSharedMemorySize, SMEM1);
    cudaFuncSetAttribute(mma_conv_kernel<true>,
                         cudaFuncAttributeMaxDynamicSharedMemorySize, SMEM2);

    // skip path first (conv2 epilogue accumulates onto it)
    skip_kernel<<<nblk, 256>>>(x, Wskip, bskip, out, n);

    // nbr transpose + fused GN1 stats/x conversion
    prep_nbr_kernel<<<nblk, 256>>>(nbr, n);
    zero_all_kernel<<<1, 160>>>();
    gn1_prep_kernel<<<1184, 256>>>(x, n);
    gn_finalize_kernel<32><<<1, 64>>>(gamma1, beta1, n);
    prepW1_kernel<<<KT, 64>>>(W1);

    // conv1 -> g_h1f16 (fp16, post-SiLU)
    mma_conv_kernel<false><<<nblk_mma, 256, SMEM1>>>(
        xf16p, nbrtp, w1p, b1p, (void*)h1p, n);

    // GN2 stats from fp16 h1
    zero_stats_kernel<<<1, 16>>>();
    gn_reduce_h1_kernel<<<1184, 256>>>(n);
    gn_finalize_kernel<64><<<1, 64>>>(gamma2, beta2, n);
    prepW2_kernel<<<KT, 64>>>(W2);

    // conv2 -> out (accumulates skip)
    mma_conv_kernel<true><<<nblk_mma, 256, SMEM2>>>(
        h1p, nbrtp, w2p, b2p, (void*)out, n);

    long main_elems = (long)n * 64;
    if ((long)out_size > main_elems) {
        long tail = (long)out_size - main_elems;
        int tb = (int)((tail + 255) / 256);
        fill_tail_kernel<<<tb, 256>>>(out, main_elems, (long)out_size);
    }
}

// round 11
// speedup vs baseline: 1.7443x; 1.1734x over previous
#include <cuda_runtime.h>
#include <cuda_fp16.h>
#include <math.h>
#include <stdint.h>

#define NMAX 500000
#define NVPAD (NMAX + 256)
#define NGROUPS 8
#define KT 27

// ---------------------------------------------------------------------------
// Device global scratch (no allocation allowed in kernel_launch)
// ---------------------------------------------------------------------------
__device__ __half g_xf16[(size_t)NMAX * 32];    // activations conv1, fp16 rows 64B
__device__ __half g_h1f16[(size_t)NMAX * 64];   // conv1 output (post-SiLU), rows 128B
__device__ __half g_w1[KT * 64 * 32];           // [k][n][c]
__device__ __half g_w2[KT * 64 * 64];           // [k][n][c]
__device__ int g_nbrt[(size_t)KT * NVPAD];      // transposed+padded nbr idx [k][v]
__device__ float g_bias1[64];
__device__ float g_bias2[64];
__device__ float g_stats[16];
__device__ float g_scale[64];
__device__ float g_bias[64];

// ---------------------------------------------------------------------------
// Helpers
// ---------------------------------------------------------------------------
__device__ __forceinline__ uint32_t smem_to_u32(const void* p) {
    uint32_t a;
    asm("{ .reg .u64 t; cvta.to.shared.u64 t, %1; cvt.u32.u64 %0, t; }" : "=r"(a) : "l"(p));
    return a;
}
__device__ __forceinline__ void cp16(uint32_t dst, const void* src) {
    asm volatile("cp.async.cg.shared.global [%0], [%1], 16;" :: "r"(dst), "l"(src));
}
#define CP_COMMIT() asm volatile("cp.async.commit_group;" ::: "memory")
#define CP_WAIT(N) asm volatile("cp.async.wait_group %0;" :: "n"(N) : "memory")

__device__ __forceinline__ void ldsm4(uint32_t* r, uint32_t addr) {
    asm volatile("ldmatrix.sync.aligned.m8n8.x4.shared.b16 {%0,%1,%2,%3}, [%4];"
                 : "=r"(r[0]), "=r"(r[1]), "=r"(r[2]), "=r"(r[3]) : "r"(addr));
}
__device__ __forceinline__ void ldsm2(uint32_t* r, uint32_t addr) {
    asm volatile("ldmatrix.sync.aligned.m8n8.x2.shared.b16 {%0,%1}, [%2];"
                 : "=r"(r[0]), "=r"(r[1]) : "r"(addr));
}
__device__ __forceinline__ void mma16816(float* d, const uint32_t* a, const uint32_t* b) {
    asm volatile(
        "mma.sync.aligned.m16n8k16.row.col.f32.f16.f16.f32 "
        "{%0,%1,%2,%3}, {%4,%5,%6,%7}, {%8,%9}, {%0,%1,%2,%3};"
        : "+f"(d[0]), "+f"(d[1]), "+f"(d[2]), "+f"(d[3])
        : "r"(a[0]), "r"(a[1]), "r"(a[2]), "r"(a[3]), "r"(b[0]), "r"(b[1]));
}
__device__ __forceinline__ float silu_f(float t) { return t / (1.f + __expf(-t)); }

// ---------------------------------------------------------------------------
// Zero kernels
// ---------------------------------------------------------------------------
__global__ void zero_all_kernel() {
    if (threadIdx.x < 16) g_stats[threadIdx.x] = 0.f;
    if (threadIdx.x >= 16 && threadIdx.x < 80) g_bias1[threadIdx.x - 16] = 0.f;
    if (threadIdx.x >= 80 && threadIdx.x < 144) g_bias2[threadIdx.x - 80] = 0.f;
}
__global__ void zero_stats_kernel() {
    if (threadIdx.x < 16) g_stats[threadIdx.x] = 0.f;
}

// ---------------------------------------------------------------------------
// Fused: GN1 stats + fp32->fp16 conversion of x (single read pass)
// ---------------------------------------------------------------------------
__global__ void gn1_prep_kernel(const float* __restrict__ x, int n) {
    int tid = blockIdx.x * blockDim.x + threadIdx.x;
    int total = gridDim.x * blockDim.x;     // multiple of 4
    int q = tid & 3;
    float s0 = 0.f, ss0 = 0.f, s1 = 0.f, ss1 = 0.f;
    long nQ = (long)n * 4;
    for (long e = tid; e < nQ; e += total) {
        long v = e >> 2;
        const float4* src = (const float4*)(x + v * 32 + q * 8);
        float4 a = src[0], b = src[1];
        uint32_t w[4];
        __half2 h;
        h = __floats2half2_rn(a.x, a.y); w[0] = *(uint32_t*)&h;
        h = __floats2half2_rn(a.z, a.w); w[1] = *(uint32_t*)&h;
        h = __floats2half2_rn(b.x, b.y); w[2] = *(uint32_t*)&h;
        h = __floats2half2_rn(b.z, b.w); w[3] = *(uint32_t*)&h;
        *(uint4*)(g_xf16 + v * 32 + q * 8) = *(uint4*)w;
        s0 += (a.x + a.y) + (a.z + a.w);
        ss0 += a.x * a.x + a.y * a.y + a.z * a.z + a.w * a.w;
        s1 += (b.x + b.y) + (b.z + b.w);
        ss1 += b.x * b.x + b.y * b.y + b.z * b.z + b.w * b.w;
    }
    __shared__ float sh[16];
    if (threadIdx.x < 16) sh[threadIdx.x] = 0.f;
    __syncthreads();
    atomicAdd(&sh[4 * q + 0], s0);
    atomicAdd(&sh[4 * q + 1], ss0);
    atomicAdd(&sh[4 * q + 2], s1);
    atomicAdd(&sh[4 * q + 3], ss1);
    __syncthreads();
    if (threadIdx.x < 16) atomicAdd(&g_stats[threadIdx.x], sh[threadIdx.x]);
}

// GN stats over g_h1f16 (fp16 rows of 64 channels)
__global__ void gn_reduce_h1_kernel(int n) {
    int tid = blockIdx.x * blockDim.x + threadIdx.x;
    int total = gridDim.x * blockDim.x;
    int sub = tid & 7;                 // 8 channels per group
    float s = 0.f, ss = 0.f;
    for (long r = tid >> 3; r < n; r += (total >> 3)) {
        uint4 H = *(const uint4*)(g_h1f16 + (size_t)r * 64 + sub * 8);
        uint32_t hu[4] = {H.x, H.y, H.z, H.w};
#pragma unroll
        for (int j = 0; j < 4; ++j) {
            __half2 h2 = *reinterpret_cast<__half2*>(&hu[j]);
            float2 f = __half22float2(h2);
            s += f.x + f.y;
            ss += f.x * f.x + f.y * f.y;
        }
    }
    __shared__ float sh[16];
    if (threadIdx.x < 16) sh[threadIdx.x] = 0.f;
    __syncthreads();
    atomicAdd(&sh[2 * sub], s);
    atomicAdd(&sh[2 * sub + 1], ss);
    __syncthreads();
    if (threadIdx.x < 16) atomicAdd(&g_stats[threadIdx.x], sh[threadIdx.x]);
}

template <int C>
__global__ void gn_finalize_kernel(const float* __restrict__ gamma,
                                   const float* __restrict__ beta, int n) {
    int c = threadIdx.x;
    if (c < C) {
        int g = c / (C / NGROUPS);
        float cnt = (float)n * (C / NGROUPS);
        float mean = g_stats[2 * g] / cnt;
        float var = g_stats[2 * g + 1] / cnt - mean * mean;
        float sc = gamma[c] * rsqrtf(var + 1e-5f);
        g_scale[c] = sc;
        g_bias[c] = beta[c] - mean * sc;
    }
}

// ---------------------------------------------------------------------------
// Prep: transpose nbr [v][k] -> g_nbrt [k][NVPAD], tail rows clamped to n-1
// ---------------------------------------------------------------------------
__global__ void prep_nbr_kernel(const int* __restrict__ nbr, int n, int npad) {
    int v = blockIdx.x * blockDim.x + threadIdx.x;
    if (v >= npad) return;
    int vs = v < n ? v : (n - 1);
#pragma unroll
    for (int k = 0; k < KT; ++k)
        g_nbrt[(size_t)k * NVPAD + v] = nbr[(size_t)vs * KT + k];
}

// ---------------------------------------------------------------------------
// Weight prep: fold GN scale into W, fp16, transpose to [k][n][c]
// ---------------------------------------------------------------------------
__global__ void prepW1_kernel(const float* __restrict__ W1) {
    int k = blockIdx.x, nn = threadIdx.x;
    float bs = 0.f;
    for (int c = 0; c < 32; ++c) {
        float w = W1[((size_t)(k * 32 + c)) * 64 + nn];
        bs += g_bias[c] * w;
        g_w1[((size_t)(k * 64 + nn)) * 32 + c] = __float2half_rn(w * g_scale[c]);
    }
    atomicAdd(&g_bias1[nn], bs);
}

__global__ void prepW2_kernel(const float* __restrict__ W2) {
    int k = blockIdx.x, nn = threadIdx.x;
    float bs = 0.f;
    for (int c = 0; c < 64; ++c) {
        float w = W2[((size_t)(k * 64 + c)) * 64 + nn];
        bs += g_bias[c] * w;
        g_w2[((size_t)(k * 64 + nn)) * 64 + c] = __float2half_rn(w * g_scale[c]);
    }
    atomicAdd(&g_bias2[nn], bs);
}

// ---------------------------------------------------------------------------
// mma.sync gather-conv, fp16 x fp16 (proven R8 structure) +
// CTA-resident index block: all 27x256 neighbor indices staged to SMEM once,
// so per-tap gathers issue off 29-cyc LDS instead of ~250-580-cyc LDG.
// One CTA = 256 voxels x 64 outputs, 8 warps, each warp m32 x n64.
// CONV2=false: CIN=32, rows 64B, 3-stage pipeline; out fp16.
// CONV2=true : CIN=64, rows 128B, 2-stage pipeline; out fp32 += skip.
// ---------------------------------------------------------------------------
template <bool CONV2>
__global__ void __launch_bounds__(256, 2)
mma_conv_kernel(const __half* __restrict__ Araw,
                const int* __restrict__ nbrt,   // [k][NVPAD]
                const __half* __restrict__ Bw,
                const float* __restrict__ biasv,
                void* __restrict__ outp, int n) {
    constexpr uint32_t IDX_BYTES = KT * 256u * 4u;         // 27648
    constexpr uint32_t A_BYTES = CONV2 ? 32768u : 16384u;  // 256 rows
    constexpr uint32_t B_BYTES = CONV2 ? 8192u : 4096u;    // 64 rows
    constexpr uint32_t STRIDE = A_BYTES + B_BYTES;
    constexpr int NSTAGE = CONV2 ? 2 : 3;

    extern __shared__ __align__(1024) char dsmem[];
    float* sbias = (float*)dsmem;
    const int* sidx = (const int*)(dsmem + 1024);
    const uint32_t idxb = smem_to_u32(dsmem + 1024);
    const uint32_t base0 = idxb + IDX_BYTES;

    const int tid = threadIdx.x;
    const int w = tid >> 5;
    const int lane = tid & 31;
    const int v0 = blockIdx.x * 256;

    if (tid < 64) sbias[tid] = biasv[tid];

    // ---- stage full index block (27 taps x 256 voxels) into SMEM ----
    {
#pragma unroll
        for (int j = 0; j < 7; ++j) {
            int c = tid + j * 256;               // 1728 chunks of 16B (4 ints)
            if (c < KT * 64) {
                int tap = c >> 6, off = (c & 63) * 4;
                cp16(idxb + (uint32_t)c * 16,
                     (const char*)nbrt + ((size_t)tap * NVPAD + v0 + off) * 4);
            }
        }
        CP_COMMIT();
        CP_WAIT(0);
        __syncthreads();
    }

    // fragment address components
    const uint32_t asel = (uint32_t)(lane >> 4);        // k-chunk low/high 8
    const int brow = lane & 7;
    const uint32_t bsel = (uint32_t)((lane >> 3) & 1);
    const int arow0 = w * 32 + (lane & 15);             // slab 0 row; slab1 = +16

    float acc[2][8][4];
#pragma unroll
    for (int s = 0; s < 2; ++s)
#pragma unroll
        for (int i = 0; i < 8; ++i)
#pragma unroll
            for (int j = 0; j < 4; ++j) acc[s][i][j] = 0.f;

    // stage loader: consecutive lanes cover one row's 16B chunks;
    // indices come from SMEM (pre-clamped in prep_nbr)
    auto load_tap = [&](int k, uint32_t stage) {
        const int* si = sidx + k * 256;
        if constexpr (CONV2) {
            const int lrow = tid >> 3, lchk = tid & 7;   // 32 rows/pass, 8 passes
#pragma unroll
            for (int p = 0; p < 8; ++p) {
                int row = p * 32 + lrow;
                int idx = si[row];
                cp16(stage + (uint32_t)row * 128 +
                         (((uint32_t)lchk ^ ((uint32_t)row & 7)) << 4),
                     (const char*)Araw + (size_t)idx * 128 + lchk * 16);
            }
#pragma unroll
            for (int j = 0; j < 2; ++j) {
                int q = tid + j * 256;               // 512 chunks of 16B
                int row = q >> 3;
                uint32_t c = (uint32_t)(q & 7);
                cp16(stage + A_BYTES + (uint32_t)row * 128 +
                         ((c ^ ((uint32_t)row & 7)) << 4),
                     (const char*)Bw + (size_t)k * 8192 + (size_t)q * 16);
            }
        } else {
            const int lrow = tid >> 2, lchk = tid & 3;   // 64 rows/pass, 4 passes
#pragma unroll
            for (int p = 0; p < 4; ++p) {
                int row = p * 64 + lrow;
                int idx = si[row];
                cp16(stage + (uint32_t)row * 64 +
                         (((uint32_t)lchk ^ ((uint32_t)row & 3)) << 4),
                     (const char*)Araw + (size_t)idx * 64 + lchk * 16);
            }
            {
                int q = tid;                          // 256 chunks of 16B
                int row = q >> 2;
                uint32_t c = (uint32_t)(q & 3);
                cp16(stage + A_BYTES + (uint32_t)row * 64 +
                         ((c ^ ((uint32_t)row & 3)) << 4),
                     (const char*)Bw + (size_t)k * 4096 + (size_t)q * 16);
            }
        }
    };

    // prologue
    load_tap(0, base0);
    CP_COMMIT();

    for (int k = 0; k < KT; ++k) {
        if constexpr (CONV2) {
            // 2-stage: top sync protects overwrite of stage holding tap k-1
            __syncthreads();
            if (k + 1 < KT) {
                load_tap(k + 1, base0 + (uint32_t)((k + 1) & 1) * STRIDE);
                CP_COMMIT();
                CP_WAIT(1);
            } else {
                CP_WAIT(0);
            }
            __syncthreads();
        } else {
            // 3-stage, single sync: load (k+1)%3 never collides with (k-1)%3
            if (k + 1 < KT) {
                load_tap(k + 1, base0 + (uint32_t)((k + 1) % 3) * STRIDE);
                CP_COMMIT();
                CP_WAIT(1);
            } else {
                CP_WAIT(0);
            }
            __syncthreads();
        }
        const uint32_t Ab = base0 + (uint32_t)(k % NSTAGE) * STRIDE;
        const uint32_t Bb = Ab + A_BYTES;
        if constexpr (CONV2) {
            uint32_t a[2][4][4];
#pragma unroll
            for (int s = 0; s < 2; ++s) {
                const int ar = arow0 + s * 16;
#pragma unroll
                for (int kc = 0; kc < 4; ++kc)
                    ldsm4(a[s][kc], Ab + (uint32_t)ar * 128 +
                                    ((((uint32_t)kc * 2 + asel) ^ ((uint32_t)ar & 7)) << 4));
            }
#pragma unroll
            for (int nt = 0; nt < 8; ++nt) {
#pragma unroll
                for (int kc = 0; kc < 4; ++kc) {
                    uint32_t b2[2];
                    ldsm2(b2, Bb + (uint32_t)nt * 1024 + (uint32_t)brow * 128 +
                                  ((((uint32_t)kc * 2 + bsel) ^ ((uint32_t)brow & 7)) << 4));
                    mma16816(acc[0][nt], a[0][kc], b2);
                    mma16816(acc[1][nt], a[1][kc], b2);
                }
            }
        } else {
            uint32_t a[2][2][4];
#pragma unroll
            for (int s = 0; s < 2; ++s) {
                const int ar = arow0 + s * 16;
#pragma unroll
                for (int kc = 0; kc < 2; ++kc)
                    ldsm4(a[s][kc], Ab + (uint32_t)ar * 64 +
                                    ((((uint32_t)kc * 2 + asel) ^ ((uint32_t)ar & 3)) << 4));
            }
#pragma unroll
            for (int nt = 0; nt < 8; ++nt) {
#pragma unroll
                for (int kc = 0; kc < 2; ++kc) {
                    uint32_t b2[2];
                    ldsm2(b2, Bb + (uint32_t)nt * 512 + (uint32_t)brow * 64 +
                                  ((((uint32_t)kc * 2 + bsel) ^ ((uint32_t)brow & 3)) << 4));
                    mma16816(acc[0][nt], a[0][kc], b2);
                    mma16816(acc[1][nt], a[1][kc], b2);
                }
            }
        }
    }

    // ---- epilogue ----
    const int g = lane >> 2, tg = lane & 3;
#pragma unroll
    for (int s = 0; s < 2; ++s) {
        const int row0 = v0 + w * 32 + s * 16 + g;
#pragma unroll
        for (int half = 0; half < 2; ++half) {
            int v = row0 + half * 8;
            if (v < n) {
                if constexpr (CONV2) {
                    float* po = (float*)outp + (size_t)v * 64;
#pragma unroll
                    for (int nt = 0; nt < 8; ++nt) {
                        int c = nt * 8 + tg * 2;
                        float2 sk = *(float2*)(po + c);
                        float2 rr;
                        rr.x = silu_f(acc[s][nt][half * 2 + 0] + sbias[c]) + sk.x;
                        rr.y = silu_f(acc[s][nt][half * 2 + 1] + sbias[c + 1]) + sk.y;
                        *(float2*)(po + c) = rr;
                    }
                } else {
                    char* basep = (char*)outp + (size_t)v * 128;
#pragma unroll
                    for (int nt = 0; nt < 8; ++nt) {
                        int c = nt * 8 + tg * 2;
                        float f0 = silu_f(acc[s][nt][half * 2 + 0] + sbias[c]);
                        float f1 = silu_f(acc[s][nt][half * 2 + 1] + sbias[c + 1]);
                        __half2 hh = __floats2half2_rn(f0, f1);
                        *(uint32_t*)(basep + c * 2) = *(uint32_t*)&hh;
                    }
                }
            }
        }
    }
}

// ---------------------------------------------------------------------------
// Scalar skip conv (proven): out = x @ Wskip + bskip
// ---------------------------------------------------------------------------
__global__ void __launch_bounds__(256, 2)
skip_kernel(const float* __restrict__ xin,
            const float* __restrict__ W,       // [32][64]
            const float* __restrict__ obias,   // [64]
            float* __restrict__ out, int n) {
    constexpr int TM = 256;
    __shared__ __align__(16) float As[32][TM + 4];
    __shared__ __align__(16) float Bs[32][64];

    const int tid = threadIdx.x;
    const int v0 = blockIdx.x * TM;
    const int vv = tid >> 3;
    const int ov = tid & 7;
    const int c4 = (tid & 7) << 2;

    float acc[8][8];
#pragma unroll
    for (int i = 0; i < 8; ++i)
#pragma unroll
        for (int j = 0; j < 8; ++j) acc[i][j] = 0.f;

    {
        const float4* Wp = (const float4*)W;
        float4* Bp = (float4*)(&Bs[0][0]);
        Bp[tid] = Wp[tid];
        Bp[tid + 256] = Wp[tid + 256];
#pragma unroll
        for (int it = 0; it < 8; ++it) {
            int v = it * 32 + (tid >> 3);
            int j = v0 + v;
            if (j >= n) j = n - 1;
            float4 xv = *(const float4*)(xin + (long)j * 32 + c4);
            As[c4 + 0][v] = xv.x;
            As[c4 + 1][v] = xv.y;
            As[c4 + 2][v] = xv.z;
            As[c4 + 3][v] = xv.w;
        }
        __syncthreads();
#pragma unroll
        for (int c = 0; c < 32; ++c) {
            float a[8], b[8];
            *(float4*)&a[0] = *(const float4*)&As[c][vv * 8];
            *(float4*)&a[4] = *(const float4*)&As[c][vv * 8 + 4];
            *(float4*)&b[0] = *(const float4*)&Bs[c][ov * 4];
            *(float4*)&b[4] = *(const float4*)&Bs[c][32 + ov * 4];
#pragma unroll
            for (int i = 0; i < 8; ++i)
#pragma unroll
                for (int j = 0; j < 8; ++j)
                    acc[i][j] = fmaf(a[i], b[j], acc[i][j]);
        }
    }
    float ob[8];
#pragma unroll
    for (int j = 0; j < 4; ++j) {
        ob[j] = obias[ov * 4 + j];
        ob[4 + j] = obias[32 + ov * 4 + j];
    }
#pragma unroll
    for (int i = 0; i < 8; ++i) {
        int v = v0 + vv * 8 + i;
        if (v < n) {
            float* po = out + (long)v * 64 + ov * 4;
            *(float4*)po = make_float4(acc[i][0] + ob[0], acc[i][1] + ob[1],
                                       acc[i][2] + ob[2], acc[i][3] + ob[3]);
            *(float4*)(po + 32) = make_float4(acc[i][4] + ob[4], acc[i][5] + ob[5],
                                              acc[i][6] + ob[6], acc[i][7] + ob[7]);
        }
    }
}

__global__ void fill_tail_kernel(float* out, long start, long end) {
    long i = start + (long)blockIdx.x * blockDim.x + threadIdx.x;
    if (i < end) out[i] = 0.f;
}

// ---------------------------------------------------------------------------
extern "C" void kernel_launch(void* const* d_in, const int* in_sizes, int n_in,
                              void* d_out, int out_size) {
    const float* x      = (const float*)d_in[0];
    const int*   nbr    = (const int*)d_in[1];
    const float* gamma1 = (const float*)d_in[2];
    const float* beta1  = (const float*)d_in[3];
    const float* W1     = (const float*)d_in[4];
    const float* gamma2 = (const float*)d_in[5];
    const float* beta2  = (const float*)d_in[6];
    const float* W2     = (const float*)d_in[7];
    const float* Wskip  = (const float*)d_in[8];
    const float* bskip  = (const float*)d_in[9];
    float* out = (float*)d_out;

    int n = in_sizes[0] / 32;
    int nblk = (n + 255) / 256;
    int nblk_mma = (n + 255) / 256;
    int npad = nblk_mma * 256;

    __half *xf16p = nullptr, *h1p = nullptr, *w1p = nullptr, *w2p = nullptr;
    float *b1p = nullptr, *b2p = nullptr;
    int *nbrtp = nullptr;
    cudaGetSymbolAddress((void**)&xf16p, g_xf16);
    cudaGetSymbolAddress((void**)&h1p, g_h1f16);
    cudaGetSymbolAddress((void**)&w1p, g_w1);
    cudaGetSymbolAddress((void**)&w2p, g_w2);
    cudaGetSymbolAddress((void**)&b1p, g_bias1);
    cudaGetSymbolAddress((void**)&b2p, g_bias2);
    cudaGetSymbolAddress((void**)&nbrtp, g_nbrt);

    const int IDXB = KT * 256 * 4;                       // 27648
    const int SMEM1 = 1024 + IDXB + 3 * (16384 + 4096);  // 90112
    const int SMEM2 = 1024 + IDXB + 2 * (32768 + 8192);  // 110592
    cudaFuncSetAttribute(mma_conv_kernel<false>,
                         cudaFuncAttributeMaxDynamicSharedMemorySize, SMEM1);
    cudaFuncSetAttribute(mma_conv_kernel<true>,
                         cudaFuncAttributeMaxDynamicSharedMemorySize, SMEM2);

    // skip path first (conv2 epilogue accumulates onto it)
    skip_kernel<<<nblk, 256>>>(x, Wskip, bskip, out, n);

    // nbr transpose (padded+clamped) + fused GN1 stats/x conversion
    prep_nbr_kernel<<<nblk_mma, 256>>>(nbr, n, npad);
    zero_all_kernel<<<1, 160>>>();
    gn1_prep_kernel<<<1184, 256>>>(x, n);
    gn_finalize_kernel<32><<<1, 64>>>(gamma1, beta1, n);
    prepW1_kernel<<<KT, 64>>>(W1);

    // conv1 -> g_h1f16 (fp16, post-SiLU)
    mma_conv_kernel<false><<<nblk_mma, 256, SMEM1>>>(
        xf16p, nbrtp, w1p, b1p, (void*)h1p, n);

    // GN2 stats from fp16 h1
    zero_stats_kernel<<<1, 16>>>();
    gn_reduce_h1_kernel<<<1184, 256>>>(n);
    gn_finalize_kernel<64><<<1, 64>>>(gamma2, beta2, n);
    prepW2_kernel<<<KT, 64>>>(W2);

    // conv2 -> out (accumulates skip)
    mma_conv_kernel<true><<<nblk_mma, 256, SMEM2>>>(
        h1p, nbrtp, w2p, b2p, (void*)out, n);

    long main_elems = (long)n * 64;
    if ((long)out_size > main_elems) {
        long tail = (long)out_size - main_elems;
        int tb = (int)((tail + 255) / 256);
        fill_tail_kernel<<<tb, 256>>>(out, main_elems, (long)out_size);
    }
}

// round 12
// speedup vs baseline: 1.7508x; 1.0037x over previous
#include <cuda_runtime.h>
#include <cuda_fp16.h>
#include <math.h>
#include <stdint.h>

#define NMAX 500000
#define NVPAD (NMAX + 256)
#define NGROUPS 8
#define KT 27

// ---------------------------------------------------------------------------
// Device global scratch (no allocation allowed in kernel_launch)
// ---------------------------------------------------------------------------
__device__ __half g_xf16[(size_t)NMAX * 32];    // activations conv1, fp16 rows 64B
__device__ __half g_h1f16[(size_t)NMAX * 64];   // conv1 output (post-SiLU), rows 128B
__device__ __half g_w1[KT * 64 * 32];           // [k][n][c]
__device__ __half g_w2[KT * 64 * 64];           // [k][n][c]
__device__ int g_nbrt[(size_t)KT * NVPAD];      // transposed+padded nbr idx [k][v]
__device__ float g_bias1[64];
__device__ float g_bias2[64];
__device__ float g_stats[16];
__device__ float g_scale[64];
__device__ float g_bias[64];

// ---------------------------------------------------------------------------
// Helpers
// ---------------------------------------------------------------------------
__device__ __forceinline__ uint32_t smem_to_u32(const void* p) {
    uint32_t a;
    asm("{ .reg .u64 t; cvta.to.shared.u64 t, %1; cvt.u32.u64 %0, t; }" : "=r"(a) : "l"(p));
    return a;
}
__device__ __forceinline__ void cp16(uint32_t dst, const void* src) {
    asm volatile("cp.async.cg.shared.global [%0], [%1], 16;" :: "r"(dst), "l"(src));
}
#define CP_COMMIT() asm volatile("cp.async.commit_group;" ::: "memory")
#define CP_WAIT(N) asm volatile("cp.async.wait_group %0;" :: "n"(N) : "memory")

__device__ __forceinline__ void ldsm4(uint32_t* r, uint32_t addr) {
    asm volatile("ldmatrix.sync.aligned.m8n8.x4.shared.b16 {%0,%1,%2,%3}, [%4];"
                 : "=r"(r[0]), "=r"(r[1]), "=r"(r[2]), "=r"(r[3]) : "r"(addr));
}
__device__ __forceinline__ void ldsm2(uint32_t* r, uint32_t addr) {
    asm volatile("ldmatrix.sync.aligned.m8n8.x2.shared.b16 {%0,%1}, [%2];"
                 : "=r"(r[0]), "=r"(r[1]) : "r"(addr));
}
__device__ __forceinline__ void mma16816(float* d, const uint32_t* a, const uint32_t* b) {
    asm volatile(
        "mma.sync.aligned.m16n8k16.row.col.f32.f16.f16.f32 "
        "{%0,%1,%2,%3}, {%4,%5,%6,%7}, {%8,%9}, {%0,%1,%2,%3};"
        : "+f"(d[0]), "+f"(d[1]), "+f"(d[2]), "+f"(d[3])
        : "r"(a[0]), "r"(a[1]), "r"(a[2]), "r"(a[3]), "r"(b[0]), "r"(b[1]));
}
__device__ __forceinline__ float silu_f(float t) { return t / (1.f + __expf(-t)); }

// ---------------------------------------------------------------------------
// Zero kernel
// ---------------------------------------------------------------------------
__global__ void zero_all_kernel() {
    if (threadIdx.x < 16) g_stats[threadIdx.x] = 0.f;
    if (threadIdx.x >= 16 && threadIdx.x < 80) g_bias1[threadIdx.x - 16] = 0.f;
    if (threadIdx.x >= 80 && threadIdx.x < 144) g_bias2[threadIdx.x - 80] = 0.f;
}

// ---------------------------------------------------------------------------
// Fused: GN1 stats + fp32->fp16 conversion of x (single read pass)
// ---------------------------------------------------------------------------
__global__ void gn1_prep_kernel(const float* __restrict__ x, int n) {
    int tid = blockIdx.x * blockDim.x + threadIdx.x;
    int total = gridDim.x * blockDim.x;     // multiple of 4
    int q = tid & 3;
    float s0 = 0.f, ss0 = 0.f, s1 = 0.f, ss1 = 0.f;
    long nQ = (long)n * 4;
    for (long e = tid; e < nQ; e += total) {
        long v = e >> 2;
        const float4* src = (const float4*)(x + v * 32 + q * 8);
        float4 a = src[0], b = src[1];
        uint32_t w[4];
        __half2 h;
        h = __floats2half2_rn(a.x, a.y); w[0] = *(uint32_t*)&h;
        h = __floats2half2_rn(a.z, a.w); w[1] = *(uint32_t*)&h;
        h = __floats2half2_rn(b.x, b.y); w[2] = *(uint32_t*)&h;
        h = __floats2half2_rn(b.z, b.w); w[3] = *(uint32_t*)&h;
        *(uint4*)(g_xf16 + v * 32 + q * 8) = *(uint4*)w;
        s0 += (a.x + a.y) + (a.z + a.w);
        ss0 += a.x * a.x + a.y * a.y + a.z * a.z + a.w * a.w;
        s1 += (b.x + b.y) + (b.z + b.w);
        ss1 += b.x * b.x + b.y * b.y + b.z * b.z + b.w * b.w;
    }
    __shared__ float sh[16];
    if (threadIdx.x < 16) sh[threadIdx.x] = 0.f;
    __syncthreads();
    atomicAdd(&sh[4 * q + 0], s0);
    atomicAdd(&sh[4 * q + 1], ss0);
    atomicAdd(&sh[4 * q + 2], s1);
    atomicAdd(&sh[4 * q + 3], ss1);
    __syncthreads();
    if (threadIdx.x < 16) atomicAdd(&g_stats[threadIdx.x], sh[threadIdx.x]);
}

// Finalize GN params; then re-zero g_stats so the next stage can accumulate.
template <int C>
__global__ void gn_finalize_kernel(const float* __restrict__ gamma,
                                   const float* __restrict__ beta, int n) {
    int c = threadIdx.x;
    float sc = 0.f, bi = 0.f;
    if (c < C) {
        int g = c / (C / NGROUPS);
        float cnt = (float)n * (C / NGROUPS);
        float mean = g_stats[2 * g] / cnt;
        float var = g_stats[2 * g + 1] / cnt - mean * mean;
        sc = gamma[c] * rsqrtf(var + 1e-5f);
        bi = beta[c] - mean * sc;
    }
    __syncthreads();
    if (c < C) {
        g_scale[c] = sc;
        g_bias[c] = bi;
    }
    if (c < 16) g_stats[c] = 0.f;
}

// ---------------------------------------------------------------------------
// Prep: transpose nbr [v][k] -> g_nbrt [k][NVPAD], tail rows clamped to n-1
// ---------------------------------------------------------------------------
__global__ void prep_nbr_kernel(const int* __restrict__ nbr, int n, int npad) {
    int v = blockIdx.x * blockDim.x + threadIdx.x;
    if (v >= npad) return;
    int vs = v < n ? v : (n - 1);
#pragma unroll
    for (int k = 0; k < KT; ++k)
        g_nbrt[(size_t)k * NVPAD + v] = nbr[(size_t)vs * KT + k];
}

// ---------------------------------------------------------------------------
// Weight prep: fold GN scale into W, fp16, transpose to [k][n][c]
// ---------------------------------------------------------------------------
__global__ void prepW1_kernel(const float* __restrict__ W1) {
    int k = blockIdx.x, nn = threadIdx.x;
    float bs = 0.f;
    for (int c = 0; c < 32; ++c) {
        float w = W1[((size_t)(k * 32 + c)) * 64 + nn];
        bs += g_bias[c] * w;
        g_w1[((size_t)(k * 64 + nn)) * 32 + c] = __float2half_rn(w * g_scale[c]);
    }
    atomicAdd(&g_bias1[nn], bs);
}

__global__ void prepW2_kernel(const float* __restrict__ W2) {
    int k = blockIdx.x, nn = threadIdx.x;
    float bs = 0.f;
    for (int c = 0; c < 64; ++c) {
        float w = W2[((size_t)(k * 64 + c)) * 64 + nn];
        bs += g_bias[c] * w;
        g_w2[((size_t)(k * 64 + nn)) * 64 + c] = __float2half_rn(w * g_scale[c]);
    }
    atomicAdd(&g_bias2[nn], bs);
}

// ---------------------------------------------------------------------------
// mma.sync gather-conv, fp16 x fp16, SMEM-resident index block (proven R11).
// One CTA = 256 voxels x 64 outputs, 8 warps, each warp m32 x n64.
// CONV2=false: CIN=32, rows 64B, 4-stage prefetch-distance-2 pipeline;
//              out fp16; epilogue accumulates GN2 stats (shfl-reduced).
// CONV2=true : CIN=64, rows 128B, 2-stage pipeline; out fp32 += skip.
// ---------------------------------------------------------------------------
template <bool CONV2>
__global__ void __launch_bounds__(256, 2)
mma_conv_kernel(const __half* __restrict__ Araw,
                const int* __restrict__ nbrt,   // [k][NVPAD]
                const __half* __restrict__ Bw,
                const float* __restrict__ biasv,
                void* __restrict__ outp, int n) {
    constexpr uint32_t IDX_BYTES = KT * 256u * 4u;         // 27648
    constexpr uint32_t A_BYTES = CONV2 ? 32768u : 16384u;  // 256 rows
    constexpr uint32_t B_BYTES = CONV2 ? 8192u : 4096u;    // 64 rows
    constexpr uint32_t STRIDE = A_BYTES + B_BYTES;
    constexpr int NSTAGE = CONV2 ? 2 : 4;

    extern __shared__ __align__(1024) char dsmem[];
    float* sbias = (float*)dsmem;
    float* shst = (float*)(dsmem + 512);     // GN2 stats staging (16 floats)
    const int* sidx = (const int*)(dsmem + 1024);
    const uint32_t idxb = smem_to_u32(dsmem + 1024);
    const uint32_t base0 = idxb + IDX_BYTES;

    const int tid = threadIdx.x;
    const int w = tid >> 5;
    const int lane = tid & 31;
    const int v0 = blockIdx.x * 256;

    if (tid < 64) sbias[tid] = biasv[tid];
    if constexpr (!CONV2) {
        if (tid < 16) shst[tid] = 0.f;
    }

    // ---- stage full index block (27 taps x 256 voxels) into SMEM ----
    {
#pragma unroll
        for (int j = 0; j < 7; ++j) {
            int c = tid + j * 256;               // 1728 chunks of 16B (4 ints)
            if (c < KT * 64) {
                int tap = c >> 6, off = (c & 63) * 4;
                cp16(idxb + (uint32_t)c * 16,
                     (const char*)nbrt + ((size_t)tap * NVPAD + v0 + off) * 4);
            }
        }
        CP_COMMIT();
        CP_WAIT(0);
        __syncthreads();
    }

    // fragment address components
    const uint32_t asel = (uint32_t)(lane >> 4);        // k-chunk low/high 8
    const int brow = lane & 7;
    const uint32_t bsel = (uint32_t)((lane >> 3) & 1);
    const int arow0 = w * 32 + (lane & 15);             // slab 0 row; slab1 = +16

    float acc[2][8][4];
#pragma unroll
    for (int s = 0; s < 2; ++s)
#pragma unroll
        for (int i = 0; i < 8; ++i)
#pragma unroll
            for (int j = 0; j < 4; ++j) acc[s][i][j] = 0.f;

    // stage loader: consecutive lanes cover one row's 16B chunks;
    // indices come from SMEM (pre-clamped in prep_nbr)
    auto load_tap = [&](int k, uint32_t stage) {
        const int* si = sidx + k * 256;
        if constexpr (CONV2) {
            const int lrow = tid >> 3, lchk = tid & 7;   // 32 rows/pass, 8 passes
#pragma unroll
            for (int p = 0; p < 8; ++p) {
                int row = p * 32 + lrow;
                int idx = si[row];
                cp16(stage + (uint32_t)row * 128 +
                         (((uint32_t)lchk ^ ((uint32_t)row & 7)) << 4),
                     (const char*)Araw + (size_t)idx * 128 + lchk * 16);
            }
#pragma unroll
            for (int j = 0; j < 2; ++j) {
                int q = tid + j * 256;               // 512 chunks of 16B
                int row = q >> 3;
                uint32_t c = (uint32_t)(q & 7);
                cp16(stage + A_BYTES + (uint32_t)row * 128 +
                         ((c ^ ((uint32_t)row & 7)) << 4),
                     (const char*)Bw + (size_t)k * 8192 + (size_t)q * 16);
            }
        } else {
            const int lrow = tid >> 2, lchk = tid & 3;   // 64 rows/pass, 4 passes
#pragma unroll
            for (int p = 0; p < 4; ++p) {
                int row = p * 64 + lrow;
                int idx = si[row];
                cp16(stage + (uint32_t)row * 64 +
                         (((uint32_t)lchk ^ ((uint32_t)row & 3)) << 4),
                     (const char*)Araw + (size_t)idx * 64 + lchk * 16);
            }
            {
                int q = tid;                          // 256 chunks of 16B
                int row = q >> 2;
                uint32_t c = (uint32_t)(q & 3);
                cp16(stage + A_BYTES + (uint32_t)row * 64 +
                         ((c ^ ((uint32_t)row & 3)) << 4),
                     (const char*)Bw + (size_t)k * 4096 + (size_t)q * 16);
            }
        }
    };

    // prologue
    if constexpr (CONV2) {
        load_tap(0, base0);
        CP_COMMIT();
    } else {
        // distance-2: preload taps 0 and 1
        load_tap(0, base0);
        CP_COMMIT();
        load_tap(1, base0 + STRIDE);
        CP_COMMIT();
    }

    for (int k = 0; k < KT; ++k) {
        if constexpr (CONV2) {
            // 2-stage: top sync protects overwrite of stage holding tap k-1
            __syncthreads();
            if (k + 1 < KT) {
                load_tap(k + 1, base0 + (uint32_t)((k + 1) & 1) * STRIDE);
                CP_COMMIT();
                CP_WAIT(1);
            } else {
                CP_WAIT(0);
            }
            __syncthreads();
        } else {
            // 4-stage, distance 2, single sync: load target (k+2)%4 is
            // distance 3 from slowest reader (k-1)%4 -> no WAR collision.
            if (k + 2 < KT) {
                load_tap(k + 2, base0 + (uint32_t)((k + 2) & 3) * STRIDE);
                CP_COMMIT();
                CP_WAIT(2);     // groups k+1, k+2 may pend; tap k complete
            } else if (k + 1 < KT) {
                CP_WAIT(1);
            } else {
                CP_WAIT(0);
            }
            __syncthreads();
        }
        const uint32_t Ab = base0 + (uint32_t)(k % NSTAGE) * STRIDE;
        const uint32_t Bb = Ab + A_BYTES;
        if constexpr (CONV2) {
            uint32_t a[2][4][4];
#pragma unroll
            for (int s = 0; s < 2; ++s) {
                const int ar = arow0 + s * 16;
#pragma unroll
                for (int kc = 0; kc < 4; ++kc)
                    ldsm4(a[s][kc], Ab + (uint32_t)ar * 128 +
                                    ((((uint32_t)kc * 2 + asel) ^ ((uint32_t)ar & 7)) << 4));
            }
#pragma unroll
            for (int nt = 0; nt < 8; ++nt) {
#pragma unroll
                for (int kc = 0; kc < 4; ++kc) {
                    uint32_t b2[2];
                    ldsm2(b2, Bb + (uint32_t)nt * 1024 + (uint32_t)brow * 128 +
                                  ((((uint32_t)kc * 2 + bsel) ^ ((uint32_t)brow & 7)) << 4));
                    mma16816(acc[0][nt], a[0][kc], b2);
                    mma16816(acc[1][nt], a[1][kc], b2);
                }
            }
        } else {
            uint32_t a[2][2][4];
#pragma unroll
            for (int s = 0; s < 2; ++s) {
                const int ar = arow0 + s * 16;
#pragma unroll
                for (int kc = 0; kc < 2; ++kc)
                    ldsm4(a[s][kc], Ab + (uint32_t)ar * 64 +
                                    ((((uint32_t)kc * 2 + asel) ^ ((uint32_t)ar & 3)) << 4));
            }
#pragma unroll
            for (int nt = 0; nt < 8; ++nt) {
#pragma unroll
                for (int kc = 0; kc < 2; ++kc) {
                    uint32_t b2[2];
                    ldsm2(b2, Bb + (uint32_t)nt * 512 + (uint32_t)brow * 64 +
                                  ((((uint32_t)kc * 2 + bsel) ^ ((uint32_t)brow & 3)) << 4));
                    mma16816(acc[0][nt], a[0][kc], b2);
                    mma16816(acc[1][nt], a[1][kc], b2);
                }
            }
        }
    }

    // ---- epilogue ----
    const int g = lane >> 2, tg = lane & 3;
    float ls[8], lss[8];
    if constexpr (!CONV2) {
#pragma unroll
        for (int nt = 0; nt < 8; ++nt) { ls[nt] = 0.f; lss[nt] = 0.f; }
    }
#pragma unroll
    for (int s = 0; s < 2; ++s) {
        const int row0 = v0 + w * 32 + s * 16 + g;
#pragma unroll
        for (int half = 0; half < 2; ++half) {
            int v = row0 + half * 8;
            if (v < n) {
                if constexpr (CONV2) {
                    float* po = (float*)outp + (size_t)v * 64;
#pragma unroll
                    for (int nt = 0; nt < 8; ++nt) {
                        int c = nt * 8 + tg * 2;
                        float2 sk = *(float2*)(po + c);
                        float2 rr;
                        rr.x = silu_f(acc[s][nt][half * 2 + 0] + sbias[c]) + sk.x;
                        rr.y = silu_f(acc[s][nt][half * 2 + 1] + sbias[c + 1]) + sk.y;
                        *(float2*)(po + c) = rr;
                    }
                } else {
                    char* basep = (char*)outp + (size_t)v * 128;
#pragma unroll
                    for (int nt = 0; nt < 8; ++nt) {
                        int c = nt * 8 + tg * 2;
                        float f0 = silu_f(acc[s][nt][half * 2 + 0] + sbias[c]);
                        float f1 = silu_f(acc[s][nt][half * 2 + 1] + sbias[c + 1]);
                        __half2 hh = __floats2half2_rn(f0, f1);
                        *(uint32_t*)(basep + c * 2) = *(uint32_t*)&hh;
                        // GN2 stats: channels nt*8.. all in group nt
                        ls[nt] += f0 + f1;
                        lss[nt] += f0 * f0 + f1 * f1;
                    }
                }
            }
        }
    }
    if constexpr (!CONV2) {
        // warp shfl reduction, then 1 shared atomic per warp per value
#pragma unroll
        for (int nt = 0; nt < 8; ++nt) {
#pragma unroll
            for (int o = 16; o > 0; o >>= 1) {
                ls[nt] += __shfl_xor_sync(0xFFFFFFFFu, ls[nt], o);
                lss[nt] += __shfl_xor_sync(0xFFFFFFFFu, lss[nt], o);
            }
        }
        if (lane == 0) {
#pragma unroll
            for (int nt = 0; nt < 8; ++nt) {
                atomicAdd(&shst[2 * nt], ls[nt]);
                atomicAdd(&shst[2 * nt + 1], lss[nt]);
            }
        }
        __syncthreads();
        if (tid < 16) atomicAdd(&g_stats[tid], shst[tid]);
    }
}

// ---------------------------------------------------------------------------
// Scalar skip conv (proven): out = x @ Wskip + bskip
// ---------------------------------------------------------------------------
__global__ void __launch_bounds__(256, 2)
skip_kernel(const float* __restrict__ xin,
            const float* __restrict__ W,       // [32][64]
            const float* __restrict__ obias,   // [64]
            float* __restrict__ out, int n) {
    constexpr int TM = 256;
    __shared__ __align__(16) float As[32][TM + 4];
    __shared__ __align__(16) float Bs[32][64];

    const int tid = threadIdx.x;
    const int v0 = blockIdx.x * TM;
    const int vv = tid >> 3;
    const int ov = tid & 7;
    const int c4 = (tid & 7) << 2;

    float acc[8][8];
#pragma unroll
    for (int i = 0; i < 8; ++i)
#pragma unroll
        for (int j = 0; j < 8; ++j) acc[i][j] = 0.f;

    {
        const float4* Wp = (const float4*)W;
        float4* Bp = (float4*)(&Bs[0][0]);
        Bp[tid] = Wp[tid];
        Bp[tid + 256] = Wp[tid + 256];
#pragma unroll
        for (int it = 0; it < 8; ++it) {
            int v = it * 32 + (tid >> 3);
            int j = v0 + v;
            if (j >= n) j = n - 1;
            float4 xv = *(const float4*)(xin + (long)j * 32 + c4);
            As[c4 + 0][v] = xv.x;
            As[c4 + 1][v] = xv.y;
            As[c4 + 2][v] = xv.z;
            As[c4 + 3][v] = xv.w;
        }
        __syncthreads();
#pragma unroll
        for (int c = 0; c < 32; ++c) {
            float a[8], b[8];
            *(float4*)&a[0] = *(const float4*)&As[c][vv * 8];
            *(float4*)&a[4] = *(const float4*)&As[c][vv * 8 + 4];
            *(float4*)&b[0] = *(const float4*)&Bs[c][ov * 4];
            *(float4*)&b[4] = *(const float4*)&Bs[c][32 + ov * 4];
#pragma unroll
            for (int i = 0; i < 8; ++i)
#pragma unroll
                for (int j = 0; j < 8; ++j)
                    acc[i][j] = fmaf(a[i], b[j], acc[i][j]);
        }
    }
    float ob[8];
#pragma unroll
    for (int j = 0; j < 4; ++j) {
        ob[j] = obias[ov * 4 + j];
        ob[4 + j] = obias[32 + ov * 4 + j];
    }
#pragma unroll
    for (int i = 0; i < 8; ++i) {
        int v = v0 + vv * 8 + i;
        if (v < n) {
            float* po = out + (long)v * 64 + ov * 4;
            *(float4*)po = make_float4(acc[i][0] + ob[0], acc[i][1] + ob[1],
                                       acc[i][2] + ob[2], acc[i][3] + ob[3]);
            *(float4*)(po + 32) = make_float4(acc[i][4] + ob[4], acc[i][5] + ob[5],
                                              acc[i][6] + ob[6], acc[i][7] + ob[7]);
        }
    }
}

__global__ void fill_tail_kernel(float* out, long start, long end) {
    long i = start + (long)blockIdx.x * blockDim.x + threadIdx.x;
    if (i < end) out[i] = 0.f;
}

// ---------------------------------------------------------------------------
extern "C" void kernel_launch(void* const* d_in, const int* in_sizes, int n_in,
                              void* d_out, int out_size) {
    const float* x      = (const float*)d_in[0];
    const int*   nbr    = (const int*)d_in[1];
    const float* gamma1 = (const float*)d_in[2];
    const float* beta1  = (const float*)d_in[3];
    const float* W1     = (const float*)d_in[4];
    const float* gamma2 = (const float*)d_in[5];
    const float* beta2  = (const float*)d_in[6];
    const float* W2     = (const float*)d_in[7];
    const float* Wskip  = (const float*)d_in[8];
    const float* bskip  = (const float*)d_in[9];
    float* out = (float*)d_out;

    int n = in_sizes[0] / 32;
    int nblk = (n + 255) / 256;
    int nblk_mma = (n + 255) / 256;
    int npad = nblk_mma * 256;

    __half *xf16p = nullptr, *h1p = nullptr, *w1p = nullptr, *w2p = nullptr;
    float *b1p = nullptr, *b2p = nullptr;
    int *nbrtp = nullptr;
    cudaGetSymbolAddress((void**)&xf16p, g_xf16);
    cudaGetSymbolAddress((void**)&h1p, g_h1f16);
    cudaGetSymbolAddress((void**)&w1p, g_w1);
    cudaGetSymbolAddress((void**)&w2p, g_w2);
    cudaGetSymbolAddress((void**)&b1p, g_bias1);
    cudaGetSymbolAddress((void**)&b2p, g_bias2);
    cudaGetSymbolAddress((void**)&nbrtp, g_nbrt);

    const int IDXB = KT * 256 * 4;                       // 27648
    const int SMEM1 = 1024 + IDXB + 4 * (16384 + 4096);  // 110592
    const int SMEM2 = 1024 + IDXB + 2 * (32768 + 8192);  // 110592
    cudaFuncSetAttribute(mma_conv_kernel<false>,
                         cudaFuncAttributeMaxDynamicSharedMemorySize, SMEM1);
    cudaFuncSetAttribute(mma_conv_kernel<true>,
                         cudaFuncAttributeMaxDynamicSharedMemorySize, SMEM2);

    // skip path first (conv2 epilogue accumulates onto it)
    skip_kernel<<<nblk, 256>>>(x, Wskip, bskip, out, n);

    // nbr transpose (padded+clamped) + fused GN1 stats/x conversion
    prep_nbr_kernel<<<nblk_mma, 256>>>(nbr, n, npad);
    zero_all_kernel<<<1, 160>>>();
    gn1_prep_kernel<<<1184, 256>>>(x, n);
    gn_finalize_kernel<32><<<1, 64>>>(gamma1, beta1, n);   // also re-zeros g_stats
    prepW1_kernel<<<KT, 64>>>(W1);

    // conv1 -> g_h1f16 (fp16, post-SiLU); epilogue accumulates GN2 stats
    mma_conv_kernel<false><<<nblk_mma, 256, SMEM1>>>(
        xf16p, nbrtp, w1p, b1p, (void*)h1p, n);

    gn_finalize_kernel<64><<<1, 64>>>(gamma2, beta2, n);
    prepW2_kernel<<<KT, 64>>>(W2);

    // conv2 -> out (accumulates skip)
    mma_conv_kernel<true><<<nblk_mma, 256, SMEM2>>>(
        h1p, nbrtp, w2p, b2p, (void*)out, n);

    long main_elems = (long)n * 64;
    if ((long)out_size > main_elems) {
        long tail = (long)out_size - main_elems;
        int tb = (int)((tail + 255) / 256);
        fill_tail_kernel<<<tb, 256>>>(out, main_elems, (long)out_size);
    }
}

// round 13
// speedup vs baseline: 2.1505x; 1.2283x over previous
#include <cuda_runtime.h>
#include <cuda_fp16.h>
#include <math.h>
#include <stdint.h>

#define NMAX 500000
#define NGROUPS 8
#define KT 27

// ---------------------------------------------------------------------------
// Device global scratch (no allocation allowed in kernel_launch)
// ---------------------------------------------------------------------------
__device__ __half g_xf16[(size_t)NMAX * 32];    // activations conv1, fp16 rows 64B
__device__ __half g_h1f16[(size_t)NMAX * 64];   // conv1 output (post-SiLU), rows 128B
__device__ __half g_skipf16[(size_t)NMAX * 64]; // skip path (fp16)
__device__ __half g_w1[KT * 64 * 32];           // [k][n][c]
__device__ __half g_w2[KT * 64 * 64];           // [k][n][c]
__device__ float g_bias1[64];
__device__ float g_bias2[64];
__device__ float g_stats[16];
__device__ float g_scale[64];
__device__ float g_bias[64];

// ---------------------------------------------------------------------------
// Helpers
// ---------------------------------------------------------------------------
__device__ __forceinline__ uint32_t smem_to_u32(const void* p) {
    uint32_t a;
    asm("{ .reg .u64 t; cvta.to.shared.u64 t, %1; cvt.u32.u64 %0, t; }" : "=r"(a) : "l"(p));
    return a;
}
__device__ __forceinline__ void cp16(uint32_t dst, const void* src) {
    asm volatile("cp.async.cg.shared.global [%0], [%1], 16;" :: "r"(dst), "l"(src));
}
#define CP_COMMIT() asm volatile("cp.async.commit_group;" ::: "memory")
#define CP_WAIT(N) asm volatile("cp.async.wait_group %0;" :: "n"(N) : "memory")

__device__ __forceinline__ void ldsm4(uint32_t* r, uint32_t addr) {
    asm volatile("ldmatrix.sync.aligned.m8n8.x4.shared.b16 {%0,%1,%2,%3}, [%4];"
                 : "=r"(r[0]), "=r"(r[1]), "=r"(r[2]), "=r"(r[3]) : "r"(addr));
}
__device__ __forceinline__ void ldsm2(uint32_t* r, uint32_t addr) {
    asm volatile("ldmatrix.sync.aligned.m8n8.x2.shared.b16 {%0,%1}, [%2];"
                 : "=r"(r[0]), "=r"(r[1]) : "r"(addr));
}
__device__ __forceinline__ void mma16816(float* d, const uint32_t* a, const uint32_t* b) {
    asm volatile(
        "mma.sync.aligned.m16n8k16.row.col.f32.f16.f16.f32 "
        "{%0,%1,%2,%3}, {%4,%5,%6,%7}, {%8,%9}, {%0,%1,%2,%3};"
        : "+f"(d[0]), "+f"(d[1]), "+f"(d[2]), "+f"(d[3])
        : "r"(a[0]), "r"(a[1]), "r"(a[2]), "r"(a[3]), "r"(b[0]), "r"(b[1]));
}
__device__ __forceinline__ float silu_f(float t) { return t / (1.f + __expf(-t)); }

// ---------------------------------------------------------------------------
// Zero kernel
// ---------------------------------------------------------------------------
__global__ void zero_all_kernel() {
    if (threadIdx.x < 16) g_stats[threadIdx.x] = 0.f;
    if (threadIdx.x >= 16 && threadIdx.x < 80) g_bias1[threadIdx.x - 16] = 0.f;
    if (threadIdx.x >= 80 && threadIdx.x < 144) g_bias2[threadIdx.x - 80] = 0.f;
}

// ---------------------------------------------------------------------------
// Fused: GN1 stats + fp32->fp16 conversion of x (single read pass)
// ---------------------------------------------------------------------------
__global__ void gn1_prep_kernel(const float* __restrict__ x, int n) {
    int tid = blockIdx.x * blockDim.x + threadIdx.x;
    int total = gridDim.x * blockDim.x;     // multiple of 4
    int q = tid & 3;
    float s0 = 0.f, ss0 = 0.f, s1 = 0.f, ss1 = 0.f;
    long nQ = (long)n * 4;
    for (long e = tid; e < nQ; e += total) {
        long v = e >> 2;
        const float4* src = (const float4*)(x + v * 32 + q * 8);
        float4 a = src[0], b = src[1];
        uint32_t w[4];
        __half2 h;
        h = __floats2half2_rn(a.x, a.y); w[0] = *(uint32_t*)&h;
        h = __floats2half2_rn(a.z, a.w); w[1] = *(uint32_t*)&h;
        h = __floats2half2_rn(b.x, b.y); w[2] = *(uint32_t*)&h;
        h = __floats2half2_rn(b.z, b.w); w[3] = *(uint32_t*)&h;
        *(uint4*)(g_xf16 + v * 32 + q * 8) = *(uint4*)w;
        s0 += (a.x + a.y) + (a.z + a.w);
        ss0 += a.x * a.x + a.y * a.y + a.z * a.z + a.w * a.w;
        s1 += (b.x + b.y) + (b.z + b.w);
        ss1 += b.x * b.x + b.y * b.y + b.z * b.z + b.w * b.w;
    }
    __shared__ float sh[16];
    if (threadIdx.x < 16) sh[threadIdx.x] = 0.f;
    __syncthreads();
    atomicAdd(&sh[4 * q + 0], s0);
    atomicAdd(&sh[4 * q + 1], ss0);
    atomicAdd(&sh[4 * q + 2], s1);
    atomicAdd(&sh[4 * q + 3], ss1);
    __syncthreads();
    if (threadIdx.x < 16) atomicAdd(&g_stats[threadIdx.x], sh[threadIdx.x]);
}

// Finalize GN params; then re-zero g_stats so the next stage can accumulate.
template <int C>
__global__ void gn_finalize_kernel(const float* __restrict__ gamma,
                                   const float* __restrict__ beta, int n) {
    int c = threadIdx.x;
    float sc = 0.f, bi = 0.f;
    if (c < C) {
        int g = c / (C / NGROUPS);
        float cnt = (float)n * (C / NGROUPS);
        float mean = g_stats[2 * g] / cnt;
        float var = g_stats[2 * g + 1] / cnt - mean * mean;
        sc = gamma[c] * rsqrtf(var + 1e-5f);
        bi = beta[c] - mean * sc;
    }
    __syncthreads();
    if (c < C) {
        g_scale[c] = sc;
        g_bias[c] = bi;
    }
    if (c < 16) g_stats[c] = 0.f;
}

// ---------------------------------------------------------------------------
// Weight prep: fold GN scale into W, fp16, transpose to [k][n][c]
// ---------------------------------------------------------------------------
__global__ void prepW1_kernel(const float* __restrict__ W1) {
    int k = blockIdx.x, nn = threadIdx.x;
    float bs = 0.f;
    for (int c = 0; c < 32; ++c) {
        float w = W1[((size_t)(k * 32 + c)) * 64 + nn];
        bs += g_bias[c] * w;
        g_w1[((size_t)(k * 64 + nn)) * 32 + c] = __float2half_rn(w * g_scale[c]);
    }
    atomicAdd(&g_bias1[nn], bs);
}

__global__ void prepW2_kernel(const float* __restrict__ W2) {
    int k = blockIdx.x, nn = threadIdx.x;
    float bs = 0.f;
    for (int c = 0; c < 64; ++c) {
        float w = W2[((size_t)(k * 64 + c)) * 64 + nn];
        bs += g_bias[c] * w;
        g_w2[((size_t)(k * 64 + nn)) * 64 + c] = __float2half_rn(w * g_scale[c]);
    }
    atomicAdd(&g_bias2[nn], bs);
}

// ---------------------------------------------------------------------------
// mma.sync gather-conv, fp16 x fp16, SMEM-resident index block staged DIRECTLY
// from the original nbr [v][k] layout (contiguous 27648B per 256-voxel CTA;
// align-down + ofs fixup; guarded scalar tail for the last CTA).
// One CTA = 256 voxels x 64 outputs, 8 warps, each warp m32 x n64.
// CONV2=false: CIN=32, rows 64B, 4-stage distance-2 pipeline; out fp16;
//              epilogue accumulates GN2 stats (shfl-reduced).
// CONV2=true : CIN=64, rows 128B, 2-stage pipeline; out fp32 = result + skip.
// ---------------------------------------------------------------------------
template <bool CONV2>
__global__ void __launch_bounds__(256, 2)
mma_conv_kernel(const __half* __restrict__ Araw,
                const int* __restrict__ nbr,    // original [v][KT]
                const __half* __restrict__ Bw,
                const float* __restrict__ biasv,
                const __half* __restrict__ skipf,  // conv2 only
                void* __restrict__ outp, int n) {
    constexpr uint32_t IDX_BYTES = 28672u;                 // >= 1729*16, padded
    constexpr uint32_t A_BYTES = CONV2 ? 32768u : 16384u;  // 256 rows
    constexpr uint32_t B_BYTES = CONV2 ? 8192u : 4096u;    // 64 rows
    constexpr uint32_t STRIDE = A_BYTES + B_BYTES;
    constexpr int NSTAGE = CONV2 ? 2 : 4;
    constexpr int NCHUNK = (256 * KT) / 4 + 1;             // 1729

    extern __shared__ __align__(1024) char dsmem[];
    float* sbias = (float*)dsmem;
    float* shst = (float*)(dsmem + 512);     // GN2 stats staging (16 floats)
    int* sidxw = (int*)(dsmem + 1024);
    const uint32_t idxb = smem_to_u32(dsmem + 1024);
    const uint32_t base0 = idxb + IDX_BYTES;

    const int tid = threadIdx.x;
    const int w = tid >> 5;
    const int lane = tid & 31;
    const int v0 = blockIdx.x * 256;
    const int lastrow = n - 1 - v0;          // >= 0; >= 255 for full CTAs

    if (tid < 64) sbias[tid] = biasv[tid];
    if constexpr (!CONV2) {
        if (tid < 16) shst[tid] = 0.f;
    }

    // ---- stage index block straight from nbr (contiguous in [v][k]) ----
    const int base_int = (v0 * KT) & ~3;     // 16B-aligned start
    const int ofs = v0 * KT - base_int;      // 0..3
    {
        const int total_ints = n * KT;
#pragma unroll
        for (int j = 0; j < 7; ++j) {
            int c = tid + j * 256;
            if (c < NCHUNK) {
                int gi = base_int + c * 4;
                if (gi + 4 <= total_ints) {
                    cp16(idxb + (uint32_t)c * 16, nbr + gi);
                } else {
#pragma unroll
                    for (int t = 0; t < 4; ++t) {
                        int g2 = gi + t;
                        sidxw[c * 4 + t] = (g2 < total_ints) ? nbr[g2] : 0;
                    }
                }
            }
        }
        CP_COMMIT();
        CP_WAIT(0);
        __syncthreads();
    }
    const int* si = sidxw + ofs;

    // fragment address components
    const uint32_t asel = (uint32_t)(lane >> 4);        // k-chunk low/high 8
    const int brow = lane & 7;
    const uint32_t bsel = (uint32_t)((lane >> 3) & 1);
    const int arow0 = w * 32 + (lane & 15);             // slab 0 row; slab1 = +16

    float acc[2][8][4];
#pragma unroll
    for (int s = 0; s < 2; ++s)
#pragma unroll
        for (int i = 0; i < 8; ++i)
#pragma unroll
            for (int j = 0; j < 4; ++j) acc[s][i][j] = 0.f;

    // stage loader: consecutive lanes cover one row's 16B chunks;
    // index = si[min(row, lastrow)*KT + k] (tail clamped)
    auto load_tap = [&](int k, uint32_t stage) {
        if constexpr (CONV2) {
            const int lrow = tid >> 3, lchk = tid & 7;   // 32 rows/pass, 8 passes
#pragma unroll
            for (int p = 0; p < 8; ++p) {
                int row = p * 32 + lrow;
                int vr = row < lastrow ? row : lastrow;
                int idx = si[vr * KT + k];
                cp16(stage + (uint32_t)row * 128 +
                         (((uint32_t)lchk ^ ((uint32_t)row & 7)) << 4),
                     (const char*)Araw + (size_t)idx * 128 + lchk * 16);
            }
#pragma unroll
            for (int j = 0; j < 2; ++j) {
                int q = tid + j * 256;               // 512 chunks of 16B
                int row = q >> 3;
                uint32_t c = (uint32_t)(q & 7);
                cp16(stage + A_BYTES + (uint32_t)row * 128 +
                         ((c ^ ((uint32_t)row & 7)) << 4),
                     (const char*)Bw + (size_t)k * 8192 + (size_t)q * 16);
            }
        } else {
            const int lrow = tid >> 2, lchk = tid & 3;   // 64 rows/pass, 4 passes
#pragma unroll
            for (int p = 0; p < 4; ++p) {
                int row = p * 64 + lrow;
                int vr = row < lastrow ? row : lastrow;
                int idx = si[vr * KT + k];
                cp16(stage + (uint32_t)row * 64 +
                         (((uint32_t)lchk ^ ((uint32_t)row & 3)) << 4),
                     (const char*)Araw + (size_t)idx * 64 + lchk * 16);
            }
            {
                int q = tid;                          // 256 chunks of 16B
                int row = q >> 2;
                uint32_t c = (uint32_t)(q & 3);
                cp16(stage + A_BYTES + (uint32_t)row * 64 +
                         ((c ^ ((uint32_t)row & 3)) << 4),
                     (const char*)Bw + (size_t)k * 4096 + (size_t)q * 16);
            }
        }
    };

    // prologue
    if constexpr (CONV2) {
        load_tap(0, base0);
        CP_COMMIT();
    } else {
        load_tap(0, base0);
        CP_COMMIT();
        load_tap(1, base0 + STRIDE);
        CP_COMMIT();
    }

    for (int k = 0; k < KT; ++k) {
        if constexpr (CONV2) {
            __syncthreads();
            if (k + 1 < KT) {
                load_tap(k + 1, base0 + (uint32_t)((k + 1) & 1) * STRIDE);
                CP_COMMIT();
                CP_WAIT(1);
            } else {
                CP_WAIT(0);
            }
            __syncthreads();
        } else {
            if (k + 2 < KT) {
                load_tap(k + 2, base0 + (uint32_t)((k + 2) & 3) * STRIDE);
                CP_COMMIT();
                CP_WAIT(2);
            } else if (k + 1 < KT) {
                CP_WAIT(1);
            } else {
                CP_WAIT(0);
            }
            __syncthreads();
        }
        const uint32_t Ab = base0 + (uint32_t)(k % NSTAGE) * STRIDE;
        const uint32_t Bb = Ab + A_BYTES;
        if constexpr (CONV2) {
            uint32_t a[2][4][4];
#pragma unroll
            for (int s = 0; s < 2; ++s) {
                const int ar = arow0 + s * 16;
#pragma unroll
                for (int kc = 0; kc < 4; ++kc)
                    ldsm4(a[s][kc], Ab + (uint32_t)ar * 128 +
                                    ((((uint32_t)kc * 2 + asel) ^ ((uint32_t)ar & 7)) << 4));
            }
#pragma unroll
            for (int nt = 0; nt < 8; ++nt) {
#pragma unroll
                for (int kc = 0; kc < 4; ++kc) {
                    uint32_t b2[2];
                    ldsm2(b2, Bb + (uint32_t)nt * 1024 + (uint32_t)brow * 128 +
                                  ((((uint32_t)kc * 2 + bsel) ^ ((uint32_t)brow & 7)) << 4));
                    mma16816(acc[0][nt], a[0][kc], b2);
                    mma16816(acc[1][nt], a[1][kc], b2);
                }
            }
        } else {
            uint32_t a[2][2][4];
#pragma unroll
            for (int s = 0; s < 2; ++s) {
                const int ar = arow0 + s * 16;
#pragma unroll
                for (int kc = 0; kc < 2; ++kc)
                    ldsm4(a[s][kc], Ab + (uint32_t)ar * 64 +
                                    ((((uint32_t)kc * 2 + asel) ^ ((uint32_t)ar & 3)) << 4));
            }
#pragma unroll
            for (int nt = 0; nt < 8; ++nt) {
#pragma unroll
                for (int kc = 0; kc < 2; ++kc) {
                    uint32_t b2[2];
                    ldsm2(b2, Bb + (uint32_t)nt * 512 + (uint32_t)brow * 64 +
                                  ((((uint32_t)kc * 2 + bsel) ^ ((uint32_t)brow & 3)) << 4));
                    mma16816(acc[0][nt], a[0][kc], b2);
                    mma16816(acc[1][nt], a[1][kc], b2);
                }
            }
        }
    }

    // ---- epilogue ----
    const int g = lane >> 2, tg = lane & 3;
    float ls[8], lss[8];
    if constexpr (!CONV2) {
#pragma unroll
        for (int nt = 0; nt < 8; ++nt) { ls[nt] = 0.f; lss[nt] = 0.f; }
    }
#pragma unroll
    for (int s = 0; s < 2; ++s) {
        const int row0 = v0 + w * 32 + s * 16 + g;
#pragma unroll
        for (int half = 0; half < 2; ++half) {
            int v = row0 + half * 8;
            if (v < n) {
                if constexpr (CONV2) {
                    float* po = (float*)outp + (size_t)v * 64;
                    const __half* sk = skipf + (size_t)v * 64;
#pragma unroll
                    for (int nt = 0; nt < 8; ++nt) {
                        int c = nt * 8 + tg * 2;
                        __half2 s2 = *(const __half2*)(sk + c);
                        float2 skf = __half22float2(s2);
                        float2 rr;
                        rr.x = silu_f(acc[s][nt][half * 2 + 0] + sbias[c]) + skf.x;
                        rr.y = silu_f(acc[s][nt][half * 2 + 1] + sbias[c + 1]) + skf.y;
                        *(float2*)(po + c) = rr;
                    }
                } else {
                    char* basep = (char*)outp + (size_t)v * 128;
#pragma unroll
                    for (int nt = 0; nt < 8; ++nt) {
                        int c = nt * 8 + tg * 2;
                        float f0 = silu_f(acc[s][nt][half * 2 + 0] + sbias[c]);
                        float f1 = silu_f(acc[s][nt][half * 2 + 1] + sbias[c + 1]);
                        __half2 hh = __floats2half2_rn(f0, f1);
                        *(uint32_t*)(basep + c * 2) = *(uint32_t*)&hh;
                        ls[nt] += f0 + f1;
                        lss[nt] += f0 * f0 + f1 * f1;
                    }
                }
            }
        }
    }
    if constexpr (!CONV2) {
#pragma unroll
        for (int nt = 0; nt < 8; ++nt) {
#pragma unroll
            for (int o = 16; o > 0; o >>= 1) {
                ls[nt] += __shfl_xor_sync(0xFFFFFFFFu, ls[nt], o);
                lss[nt] += __shfl_xor_sync(0xFFFFFFFFu, lss[nt], o);
            }
        }
        if (lane == 0) {
#pragma unroll
            for (int nt = 0; nt < 8; ++nt) {
                atomicAdd(&shst[2 * nt], ls[nt]);
                atomicAdd(&shst[2 * nt + 1], lss[nt]);
            }
        }
        __syncthreads();
        if (tid < 16) atomicAdd(&g_stats[tid], shst[tid]);
    }
}

// ---------------------------------------------------------------------------
// Scalar skip conv: g_skipf16 = fp16(x @ Wskip + bskip)
// ---------------------------------------------------------------------------
__global__ void __launch_bounds__(256, 2)
skip_kernel(const float* __restrict__ xin,
            const float* __restrict__ W,       // [32][64]
            const float* __restrict__ obias,   // [64]
            int n) {
    constexpr int TM = 256;
    __shared__ __align__(16) float As[32][TM + 4];
    __shared__ __align__(16) float Bs[32][64];

    const int tid = threadIdx.x;
    const int v0 = blockIdx.x * TM;
    const int vv = tid >> 3;
    const int ov = tid & 7;
    const int c4 = (tid & 7) << 2;

    float acc[8][8];
#pragma unroll
    for (int i = 0; i < 8; ++i)
#pragma unroll
        for (int j = 0; j < 8; ++j) acc[i][j] = 0.f;

    {
        const float4* Wp = (const float4*)W;
        float4* Bp = (float4*)(&Bs[0][0]);
        Bp[tid] = Wp[tid];
        Bp[tid + 256] = Wp[tid + 256];
#pragma unroll
        for (int it = 0; it < 8; ++it) {
            int v = it * 32 + (tid >> 3);
            int j = v0 + v;
            if (j >= n) j = n - 1;
            float4 xv = *(const float4*)(xin + (long)j * 32 + c4);
            As[c4 + 0][v] = xv.x;
            As[c4 + 1][v] = xv.y;
            As[c4 + 2][v] = xv.z;
            As[c4 + 3][v] = xv.w;
        }
        __syncthreads();
#pragma unroll
        for (int c = 0; c < 32; ++c) {
            float a[8], b[8];
            *(float4*)&a[0] = *(const float4*)&As[c][vv * 8];
            *(float4*)&a[4] = *(const float4*)&As[c][vv * 8 + 4];
            *(float4*)&b[0] = *(const float4*)&Bs[c][ov * 4];
            *(float4*)&b[4] = *(const float4*)&Bs[c][32 + ov * 4];
#pragma unroll
            for (int i = 0; i < 8; ++i)
#pragma unroll
                for (int j = 0; j < 8; ++j)
                    acc[i][j] = fmaf(a[i], b[j], acc[i][j]);
        }
    }
    float ob[8];
#pragma unroll
    for (int j = 0; j < 4; ++j) {
        ob[j] = obias[ov * 4 + j];
        ob[4 + j] = obias[32 + ov * 4 + j];
    }
#pragma unroll
    for (int i = 0; i < 8; ++i) {
        int v = v0 + vv * 8 + i;
        if (v < n) {
            __half* po = g_skipf16 + (size_t)v * 64;
            __half2 h0 = __floats2half2_rn(acc[i][0] + ob[0], acc[i][1] + ob[1]);
            __half2 h1 = __floats2half2_rn(acc[i][2] + ob[2], acc[i][3] + ob[3]);
            __half2 h2 = __floats2half2_rn(acc[i][4] + ob[4], acc[i][5] + ob[5]);
            __half2 h3 = __floats2half2_rn(acc[i][6] + ob[6], acc[i][7] + ob[7]);
            uint2 lo = make_uint2(*(uint32_t*)&h0, *(uint32_t*)&h1);
            uint2 hi = make_uint2(*(uint32_t*)&h2, *(uint32_t*)&h3);
            *(uint2*)(po + ov * 4) = lo;
            *(uint2*)(po + 32 + ov * 4) = hi;
        }
    }
}

__global__ void fill_tail_kernel(float* out, long start, long end) {
    long i = start + (long)blockIdx.x * blockDim.x + threadIdx.x;
    if (i < end) out[i] = 0.f;
}

// ---------------------------------------------------------------------------
extern "C" void kernel_launch(void* const* d_in, const int* in_sizes, int n_in,
                              void* d_out, int out_size) {
    const float* x      = (const float*)d_in[0];
    const int*   nbr    = (const int*)d_in[1];
    const float* gamma1 = (const float*)d_in[2];
    const float* beta1  = (const float*)d_in[3];
    const float* W1     = (const float*)d_in[4];
    const float* gamma2 = (const float*)d_in[5];
    const float* beta2  = (const float*)d_in[6];
    const float* W2     = (const float*)d_in[7];
    const float* Wskip  = (const float*)d_in[8];
    const float* bskip  = (const float*)d_in[9];
    float* out = (float*)d_out;

    int n = in_sizes[0] / 32;
    int nblk = (n + 255) / 256;
    int nblk_mma = (n + 255) / 256;

    __half *xf16p = nullptr, *h1p = nullptr, *skp = nullptr,
           *w1p = nullptr, *w2p = nullptr;
    float *b1p = nullptr, *b2p = nullptr;
    cudaGetSymbolAddress((void**)&xf16p, g_xf16);
    cudaGetSymbolAddress((void**)&h1p, g_h1f16);
    cudaGetSymbolAddress((void**)&skp, g_skipf16);
    cudaGetSymbolAddress((void**)&w1p, g_w1);
    cudaGetSymbolAddress((void**)&w2p, g_w2);
    cudaGetSymbolAddress((void**)&b1p, g_bias1);
    cudaGetSymbolAddress((void**)&b2p, g_bias2);

    const int IDXB = 28672;
    const int SMEM1 = 1024 + IDXB + 4 * (16384 + 4096);  // 111616
    const int SMEM2 = 1024 + IDXB + 2 * (32768 + 8192);  // 111616
    cudaFuncSetAttribute(mma_conv_kernel<false>,
                         cudaFuncAttributeMaxDynamicSharedMemorySize, SMEM1);
    cudaFuncSetAttribute(mma_conv_kernel<true>,
                         cudaFuncAttributeMaxDynamicSharedMemorySize, SMEM2);

    // skip path -> g_skipf16 (fp16)
    skip_kernel<<<nblk, 256>>>(x, Wskip, bskip, n);

    // fused GN1 stats + x fp16 conversion
    zero_all_kernel<<<1, 160>>>();
    gn1_prep_kernel<<<1184, 256>>>(x, n);
    gn_finalize_kernel<32><<<1, 64>>>(gamma1, beta1, n);   // also re-zeros g_stats
    prepW1_kernel<<<KT, 64>>>(W1);

    // conv1 -> g_h1f16 (fp16, post-SiLU); epilogue accumulates GN2 stats
    mma_conv_kernel<false><<<nblk_mma, 256, SMEM1>>>(
        xf16p, nbr, w1p, b1p, nullptr, (void*)h1p, n);

    gn_finalize_kernel<64><<<1, 64>>>(gamma2, beta2, n);
    prepW2_kernel<<<KT, 64>>>(W2);

    // conv2 -> out = silu(conv2) + skip
    mma_conv_kernel<true><<<nblk_mma, 256, SMEM2>>>(
        h1p, nbr, w2p, b2p, skp, (void*)out, n);

    long main_elems = (long)n * 64;
    if ((long)out_size > main_elems) {
        long tail = (long)out_size - main_elems;
        int tb = (int)((tail + 255) / 256);
        fill_tail_kernel<<<tb, 256>>>(out, main_elems, (long)out_size);
    }
}

// round 14
// speedup vs baseline: 2.2267x; 1.0354x over previous
#include <cuda_runtime.h>
#include <cuda_fp16.h>
#include <math.h>
#include <stdint.h>

#define NMAX 500000
#define NGROUPS 8
#define KT 27

// ---------------------------------------------------------------------------
// Device global scratch (no allocation allowed in kernel_launch)
// ---------------------------------------------------------------------------
__device__ __half g_xf16[(size_t)NMAX * 32];    // activations conv1, fp16 rows 64B
__device__ __half g_h1f16[(size_t)NMAX * 64];   // conv1 output (post-SiLU), rows 128B
__device__ __half g_skipf16[(size_t)NMAX * 64]; // skip path (fp16)
__device__ __half g_w1[KT * 64 * 32];           // [k][n][c]
__device__ __half g_w2[KT * 64 * 64];           // [k][n][c]
__device__ __half g_ws[64 * 32];                // Wskip transposed [n][c]
__device__ float g_bias1[64];
__device__ float g_bias2[64];
__device__ float g_stats[16];
__device__ float g_scale[64];
__device__ float g_bias[64];

// ---------------------------------------------------------------------------
// Helpers
// ---------------------------------------------------------------------------
__device__ __forceinline__ uint32_t smem_to_u32(const void* p) {
    uint32_t a;
    asm("{ .reg .u64 t; cvta.to.shared.u64 t, %1; cvt.u32.u64 %0, t; }" : "=r"(a) : "l"(p));
    return a;
}
__device__ __forceinline__ void cp16(uint32_t dst, const void* src) {
    asm volatile("cp.async.cg.shared.global [%0], [%1], 16;" :: "r"(dst), "l"(src));
}
#define CP_COMMIT() asm volatile("cp.async.commit_group;" ::: "memory")
#define CP_WAIT(N) asm volatile("cp.async.wait_group %0;" :: "n"(N) : "memory")

__device__ __forceinline__ void ldsm4(uint32_t* r, uint32_t addr) {
    asm volatile("ldmatrix.sync.aligned.m8n8.x4.shared.b16 {%0,%1,%2,%3}, [%4];"
                 : "=r"(r[0]), "=r"(r[1]), "=r"(r[2]), "=r"(r[3]) : "r"(addr));
}
__device__ __forceinline__ void ldsm2(uint32_t* r, uint32_t addr) {
    asm volatile("ldmatrix.sync.aligned.m8n8.x2.shared.b16 {%0,%1}, [%2];"
                 : "=r"(r[0]), "=r"(r[1]) : "r"(addr));
}
__device__ __forceinline__ void mma16816(float* d, const uint32_t* a, const uint32_t* b) {
    asm volatile(
        "mma.sync.aligned.m16n8k16.row.col.f32.f16.f16.f32 "
        "{%0,%1,%2,%3}, {%4,%5,%6,%7}, {%8,%9}, {%0,%1,%2,%3};"
        : "+f"(d[0]), "+f"(d[1]), "+f"(d[2]), "+f"(d[3])
        : "r"(a[0]), "r"(a[1]), "r"(a[2]), "r"(a[3]), "r"(b[0]), "r"(b[1]));
}
__device__ __forceinline__ float silu_f(float t) { return t / (1.f + __expf(-t)); }

// ---------------------------------------------------------------------------
// Zero kernel
// ---------------------------------------------------------------------------
__global__ void zero_all_kernel() {
    if (threadIdx.x < 16) g_stats[threadIdx.x] = 0.f;
    if (threadIdx.x >= 16 && threadIdx.x < 80) g_bias1[threadIdx.x - 16] = 0.f;
    if (threadIdx.x >= 80 && threadIdx.x < 144) g_bias2[threadIdx.x - 80] = 0.f;
}

// ---------------------------------------------------------------------------
// Fused: GN1 stats + fp32->fp16 conversion of x (single read pass)
// ---------------------------------------------------------------------------
__global__ void gn1_prep_kernel(const float* __restrict__ x, int n) {
    int tid = blockIdx.x * blockDim.x + threadIdx.x;
    int total = gridDim.x * blockDim.x;     // multiple of 4
    int q = tid & 3;
    float s0 = 0.f, ss0 = 0.f, s1 = 0.f, ss1 = 0.f;
    long nQ = (long)n * 4;
    for (long e = tid; e < nQ; e += total) {
        long v = e >> 2;
        const float4* src = (const float4*)(x + v * 32 + q * 8);
        float4 a = src[0], b = src[1];
        uint32_t w[4];
        __half2 h;
        h = __floats2half2_rn(a.x, a.y); w[0] = *(uint32_t*)&h;
        h = __floats2half2_rn(a.z, a.w); w[1] = *(uint32_t*)&h;
        h = __floats2half2_rn(b.x, b.y); w[2] = *(uint32_t*)&h;
        h = __floats2half2_rn(b.z, b.w); w[3] = *(uint32_t*)&h;
        *(uint4*)(g_xf16 + v * 32 + q * 8) = *(uint4*)w;
        s0 += (a.x + a.y) + (a.z + a.w);
        ss0 += a.x * a.x + a.y * a.y + a.z * a.z + a.w * a.w;
        s1 += (b.x + b.y) + (b.z + b.w);
        ss1 += b.x * b.x + b.y * b.y + b.z * b.z + b.w * b.w;
    }
    __shared__ float sh[16];
    if (threadIdx.x < 16) sh[threadIdx.x] = 0.f;
    __syncthreads();
    atomicAdd(&sh[4 * q + 0], s0);
    atomicAdd(&sh[4 * q + 1], ss0);
    atomicAdd(&sh[4 * q + 2], s1);
    atomicAdd(&sh[4 * q + 3], ss1);
    __syncthreads();
    if (threadIdx.x < 16) atomicAdd(&g_stats[threadIdx.x], sh[threadIdx.x]);
}

// Finalize GN params; then re-zero g_stats so the next stage can accumulate.
template <int C>
__global__ void gn_finalize_kernel(const float* __restrict__ gamma,
                                   const float* __restrict__ beta, int n) {
    int c = threadIdx.x;
    float sc = 0.f, bi = 0.f;
    if (c < C) {
        int g = c / (C / NGROUPS);
        float cnt = (float)n * (C / NGROUPS);
        float mean = g_stats[2 * g] / cnt;
        float var = g_stats[2 * g + 1] / cnt - mean * mean;
        sc = gamma[c] * rsqrtf(var + 1e-5f);
        bi = beta[c] - mean * sc;
    }
    __syncthreads();
    if (c < C) {
        g_scale[c] = sc;
        g_bias[c] = bi;
    }
    if (c < 16) g_stats[c] = 0.f;
}

// ---------------------------------------------------------------------------
// Weight prep: fold GN scale into W, fp16, transpose to [k][n][c]
// ---------------------------------------------------------------------------
__global__ void prepW1_kernel(const float* __restrict__ W1) {
    int k = blockIdx.x, nn = threadIdx.x;
    float bs = 0.f;
    for (int c = 0; c < 32; ++c) {
        float w = W1[((size_t)(k * 32 + c)) * 64 + nn];
        bs += g_bias[c] * w;
        g_w1[((size_t)(k * 64 + nn)) * 32 + c] = __float2half_rn(w * g_scale[c]);
    }
    atomicAdd(&g_bias1[nn], bs);
}

__global__ void prepW2_kernel(const float* __restrict__ W2) {
    int k = blockIdx.x, nn = threadIdx.x;
    float bs = 0.f;
    for (int c = 0; c < 64; ++c) {
        float w = W2[((size_t)(k * 64 + c)) * 64 + nn];
        bs += g_bias[c] * w;
        g_w2[((size_t)(k * 64 + nn)) * 64 + c] = __float2half_rn(w * g_scale[c]);
    }
    atomicAdd(&g_bias2[nn], bs);
}

// Wskip [32][64] fp32 -> g_ws [n=64][c=32] fp16 (no GN folding)
__global__ void prepWs_kernel(const float* __restrict__ Wskip) {
    int nn = threadIdx.x;
    for (int c = 0; c < 32; ++c)
        g_ws[nn * 32 + c] = __float2half_rn(Wskip[(size_t)c * 64 + nn]);
}

// ---------------------------------------------------------------------------
// Skip path via MMA: g_skipf16[v] = fp16(xf16[v] @ Ws + bskip)
// One CTA = 256 voxels, 8 warps m32 x n64, single stage (contiguous rows).
// ---------------------------------------------------------------------------
__global__ void __launch_bounds__(256, 2)
skip_mma_kernel(const __half* __restrict__ Araw,   // g_xf16
                const __half* __restrict__ Bw,     // g_ws
                const float* __restrict__ obias,   // bskip
                int n) {
    extern __shared__ __align__(1024) char dsmem[];
    float* sbias = (float*)dsmem;
    const uint32_t Ab = smem_to_u32(dsmem + 1024);
    const uint32_t Bb = Ab + 16384u;

    const int tid = threadIdx.x;
    const int w = tid >> 5;
    const int lane = tid & 31;
    const int v0 = blockIdx.x * 256;
    const int lastrow = n - 1 - v0;

    if (tid < 64) sbias[tid] = obias[tid];

    // stage A (contiguous 256 rows x 64B) + B (64 rows x 64B)
    {
        const int lrow = tid >> 2, lchk = tid & 3;
#pragma unroll
        for (int p = 0; p < 4; ++p) {
            int row = p * 64 + lrow;
            int vr = row < lastrow ? row : lastrow;
            cp16(Ab + (uint32_t)row * 64 +
                     (((uint32_t)lchk ^ ((uint32_t)row & 3)) << 4),
                 (const char*)Araw + ((size_t)(v0 + vr) * 32 + lchk * 8) * 2);
        }
        {
            int q = tid;                          // 256 chunks
            int row = q >> 2;
            uint32_t c = (uint32_t)(q & 3);
            cp16(Bb + (uint32_t)row * 64 + ((c ^ ((uint32_t)row & 3)) << 4),
                 (const char*)Bw + (size_t)q * 16);
        }
        CP_COMMIT();
        CP_WAIT(0);
        __syncthreads();
    }

    const uint32_t asel = (uint32_t)(lane >> 4);
    const int brow = lane & 7;
    const uint32_t bsel = (uint32_t)((lane >> 3) & 1);
    const int arow0 = w * 32 + (lane & 15);

    float acc[2][8][4];
#pragma unroll
    for (int s = 0; s < 2; ++s)
#pragma unroll
        for (int i = 0; i < 8; ++i)
#pragma unroll
            for (int j = 0; j < 4; ++j) acc[s][i][j] = 0.f;

    uint32_t a[2][2][4];
#pragma unroll
    for (int s = 0; s < 2; ++s) {
        const int ar = arow0 + s * 16;
#pragma unroll
        for (int kc = 0; kc < 2; ++kc)
            ldsm4(a[s][kc], Ab + (uint32_t)ar * 64 +
                            ((((uint32_t)kc * 2 + asel) ^ ((uint32_t)ar & 3)) << 4));
    }
#pragma unroll
    for (int nt = 0; nt < 8; ++nt) {
#pragma unroll
        for (int kc = 0; kc < 2; ++kc) {
            uint32_t b2[2];
            ldsm2(b2, Bb + (uint32_t)nt * 512 + (uint32_t)brow * 64 +
                          ((((uint32_t)kc * 2 + bsel) ^ ((uint32_t)brow & 3)) << 4));
            mma16816(acc[0][nt], a[0][kc], b2);
            mma16816(acc[1][nt], a[1][kc], b2);
        }
    }

    const int g = lane >> 2, tg = lane & 3;
#pragma unroll
    for (int s = 0; s < 2; ++s) {
        const int row0 = v0 + w * 32 + s * 16 + g;
#pragma unroll
        for (int half = 0; half < 2; ++half) {
            int v = row0 + half * 8;
            if (v < n) {
                __half* po = g_skipf16 + (size_t)v * 64;
#pragma unroll
                for (int nt = 0; nt < 8; ++nt) {
                    int c = nt * 8 + tg * 2;
                    __half2 hh = __floats2half2_rn(
                        acc[s][nt][half * 2 + 0] + sbias[c],
                        acc[s][nt][half * 2 + 1] + sbias[c + 1]);
                    *(uint32_t*)(po + c) = *(uint32_t*)&hh;
                }
            }
        }
    }
}

// ---------------------------------------------------------------------------
// mma.sync gather-conv (proven R13): fp16 x fp16, SMEM index block staged
// straight from nbr [v][k]; warp m32 x n64.
// CONV2=false: CIN=32, 4-stage distance-2; out fp16; GN2 stats in epilogue.
// CONV2=true : CIN=64, 2-stage; out fp32 = silu(conv)+skip.
// ---------------------------------------------------------------------------
template <bool CONV2>
__global__ void __launch_bounds__(256, 2)
mma_conv_kernel(const __half* __restrict__ Araw,
                const int* __restrict__ nbr,    // original [v][KT]
                const __half* __restrict__ Bw,
                const float* __restrict__ biasv,
                const __half* __restrict__ skipf,  // conv2 only
                void* __restrict__ outp, int n) {
    constexpr uint32_t IDX_BYTES = 28672u;                 // >= 1729*16, padded
    constexpr uint32_t A_BYTES = CONV2 ? 32768u : 16384u;  // 256 rows
    constexpr uint32_t B_BYTES = CONV2 ? 8192u : 4096u;    // 64 rows
    constexpr uint32_t STRIDE = A_BYTES + B_BYTES;
    constexpr int NSTAGE = CONV2 ? 2 : 4;
    constexpr int NCHUNK = (256 * KT) / 4 + 1;             // 1729

    extern __shared__ __align__(1024) char dsmem[];
    float* sbias = (float*)dsmem;
    float* shst = (float*)(dsmem + 512);     // GN2 stats staging (16 floats)
    int* sidxw = (int*)(dsmem + 1024);
    const uint32_t idxb = smem_to_u32(dsmem + 1024);
    const uint32_t base0 = idxb + IDX_BYTES;

    const int tid = threadIdx.x;
    const int w = tid >> 5;
    const int lane = tid & 31;
    const int v0 = blockIdx.x * 256;
    const int lastrow = n - 1 - v0;          // >= 0; >= 255 for full CTAs

    if (tid < 64) sbias[tid] = biasv[tid];
    if constexpr (!CONV2) {
        if (tid < 16) shst[tid] = 0.f;
    }

    // ---- stage index block straight from nbr (contiguous in [v][k]) ----
    const int base_int = (v0 * KT) & ~3;     // 16B-aligned start
    const int ofs = v0 * KT - base_int;      // 0..3
    {
        const int total_ints = n * KT;
#pragma unroll
        for (int j = 0; j < 7; ++j) {
            int c = tid + j * 256;
            if (c < NCHUNK) {
                int gi = base_int + c * 4;
                if (gi + 4 <= total_ints) {
                    cp16(idxb + (uint32_t)c * 16, nbr + gi);
                } else {
#pragma unroll
                    for (int t = 0; t < 4; ++t) {
                        int g2 = gi + t;
                        sidxw[c * 4 + t] = (g2 < total_ints) ? nbr[g2] : 0;
                    }
                }
            }
        }
        CP_COMMIT();
        CP_WAIT(0);
        __syncthreads();
    }
    const int* si = sidxw + ofs;

    // fragment address components
    const uint32_t asel = (uint32_t)(lane >> 4);        // k-chunk low/high 8
    const int brow = lane & 7;
    const uint32_t bsel = (uint32_t)((lane >> 3) & 1);
    const int arow0 = w * 32 + (lane & 15);             // slab 0 row; slab1 = +16

    float acc[2][8][4];
#pragma unroll
    for (int s = 0; s < 2; ++s)
#pragma unroll
        for (int i = 0; i < 8; ++i)
#pragma unroll
            for (int j = 0; j < 4; ++j) acc[s][i][j] = 0.f;

    // stage loader: consecutive lanes cover one row's 16B chunks;
    // index = si[min(row, lastrow)*KT + k] (tail clamped)
    auto load_tap = [&](int k, uint32_t stage) {
        if constexpr (CONV2) {
            const int lrow = tid >> 3, lchk = tid & 7;   // 32 rows/pass, 8 passes
#pragma unroll
            for (int p = 0; p < 8; ++p) {
                int row = p * 32 + lrow;
                int vr = row < lastrow ? row : lastrow;
                int idx = si[vr * KT + k];
                cp16(stage + (uint32_t)row * 128 +
                         (((uint32_t)lchk ^ ((uint32_t)row & 7)) << 4),
                     (const char*)Araw + (size_t)idx * 128 + lchk * 16);
            }
#pragma unroll
            for (int j = 0; j < 2; ++j) {
                int q = tid + j * 256;               // 512 chunks of 16B
                int row = q >> 3;
                uint32_t c = (uint32_t)(q & 7);
                cp16(stage + A_BYTES + (uint32_t)row * 128 +
                         ((c ^ ((uint32_t)row & 7)) << 4),
                     (const char*)Bw + (size_t)k * 8192 + (size_t)q * 16);
            }
        } else {
            const int lrow = tid >> 2, lchk = tid & 3;   // 64 rows/pass, 4 passes
#pragma unroll
            for (int p = 0; p < 4; ++p) {
                int row = p * 64 + lrow;
                int vr = row < lastrow ? row : lastrow;
                int idx = si[vr * KT + k];
                cp16(stage + (uint32_t)row * 64 +
                         (((uint32_t)lchk ^ ((uint32_t)row & 3)) << 4),
                     (const char*)Araw + (size_t)idx * 64 + lchk * 16);
            }
            {
                int q = tid;                          // 256 chunks of 16B
                int row = q >> 2;
                uint32_t c = (uint32_t)(q & 3);
                cp16(stage + A_BYTES + (uint32_t)row * 64 +
                         ((c ^ ((uint32_t)row & 3)) << 4),
                     (const char*)Bw + (size_t)k * 4096 + (size_t)q * 16);
            }
        }
    };

    // prologue
    if constexpr (CONV2) {
        load_tap(0, base0);
        CP_COMMIT();
    } else {
        load_tap(0, base0);
        CP_COMMIT();
        load_tap(1, base0 + STRIDE);
        CP_COMMIT();
    }

    for (int k = 0; k < KT; ++k) {
        if constexpr (CONV2) {
            __syncthreads();
            if (k + 1 < KT) {
                load_tap(k + 1, base0 + (uint32_t)((k + 1) & 1) * STRIDE);
                CP_COMMIT();
                CP_WAIT(1);
            } else {
                CP_WAIT(0);
            }
            __syncthreads();
        } else {
            if (k + 2 < KT) {
                load_tap(k + 2, base0 + (uint32_t)((k + 2) & 3) * STRIDE);
                CP_COMMIT();
                CP_WAIT(2);
            } else if (k + 1 < KT) {
                CP_WAIT(1);
            } else {
                CP_WAIT(0);
            }
            __syncthreads();
        }
        const uint32_t Ab = base0 + (uint32_t)(k % NSTAGE) * STRIDE;
        const uint32_t Bb = Ab + A_BYTES;
        if constexpr (CONV2) {
            uint32_t a[2][4][4];
#pragma unroll
            for (int s = 0; s < 2; ++s) {
                const int ar = arow0 + s * 16;
#pragma unroll
                for (int kc = 0; kc < 4; ++kc)
                    ldsm4(a[s][kc], Ab + (uint32_t)ar * 128 +
                                    ((((uint32_t)kc * 2 + asel) ^ ((uint32_t)ar & 7)) << 4));
            }
#pragma unroll
            for (int nt = 0; nt < 8; ++nt) {
#pragma unroll
                for (int kc = 0; kc < 4; ++kc) {
                    uint32_t b2[2];
                    ldsm2(b2, Bb + (uint32_t)nt * 1024 + (uint32_t)brow * 128 +
                                  ((((uint32_t)kc * 2 + bsel) ^ ((uint32_t)brow & 7)) << 4));
                    mma16816(acc[0][nt], a[0][kc], b2);
                    mma16816(acc[1][nt], a[1][kc], b2);
                }
            }
        } else {
            uint32_t a[2][2][4];
#pragma unroll
            for (int s = 0; s < 2; ++s) {
                const int ar = arow0 + s * 16;
#pragma unroll
                for (int kc = 0; kc < 2; ++kc)
                    ldsm4(a[s][kc], Ab + (uint32_t)ar * 64 +
                                    ((((uint32_t)kc * 2 + asel) ^ ((uint32_t)ar & 3)) << 4));
            }
#pragma unroll
            for (int nt = 0; nt < 8; ++nt) {
#pragma unroll
                for (int kc = 0; kc < 2; ++kc) {
                    uint32_t b2[2];
                    ldsm2(b2, Bb + (uint32_t)nt * 512 + (uint32_t)brow * 64 +
                                  ((((uint32_t)kc * 2 + bsel) ^ ((uint32_t)brow & 3)) << 4));
                    mma16816(acc[0][nt], a[0][kc], b2);
                    mma16816(acc[1][nt], a[1][kc], b2);
                }
            }
        }
    }

    // ---- epilogue ----
    const int g = lane >> 2, tg = lane & 3;
    float ls[8], lss[8];
    if constexpr (!CONV2) {
#pragma unroll
        for (int nt = 0; nt < 8; ++nt) { ls[nt] = 0.f; lss[nt] = 0.f; }
    }
#pragma unroll
    for (int s = 0; s < 2; ++s) {
        const int row0 = v0 + w * 32 + s * 16 + g;
#pragma unroll
        for (int half = 0; half < 2; ++half) {
            int v = row0 + half * 8;
            if (v < n) {
                if constexpr (CONV2) {
                    float* po = (float*)outp + (size_t)v * 64;
                    const __half* sk = skipf + (size_t)v * 64;
#pragma unroll
                    for (int nt = 0; nt < 8; ++nt) {
                        int c = nt * 8 + tg * 2;
                        __half2 s2 = *(const __half2*)(sk + c);
                        float2 skf = __half22float2(s2);
                        float2 rr;
                        rr.x = silu_f(acc[s][nt][half * 2 + 0] + sbias[c]) + skf.x;
                        rr.y = silu_f(acc[s][nt][half * 2 + 1] + sbias[c + 1]) + skf.y;
                        *(float2*)(po + c) = rr;
                    }
                } else {
                    char* basep = (char*)outp + (size_t)v * 128;
#pragma unroll
                    for (int nt = 0; nt < 8; ++nt) {
                        int c = nt * 8 + tg * 2;
                        float f0 = silu_f(acc[s][nt][half * 2 + 0] + sbias[c]);
                        float f1 = silu_f(acc[s][nt][half * 2 + 1] + sbias[c + 1]);
                        __half2 hh = __floats2half2_rn(f0, f1);
                        *(uint32_t*)(basep + c * 2) = *(uint32_t*)&hh;
                        ls[nt] += f0 + f1;
                        lss[nt] += f0 * f0 + f1 * f1;
                    }
                }
            }
        }
    }
    if constexpr (!CONV2) {
#pragma unroll
        for (int nt = 0; nt < 8; ++nt) {
#pragma unroll
            for (int o = 16; o > 0; o >>= 1) {
                ls[nt] += __shfl_xor_sync(0xFFFFFFFFu, ls[nt], o);
                lss[nt] += __shfl_xor_sync(0xFFFFFFFFu, lss[nt], o);
            }
        }
        if (lane == 0) {
#pragma unroll
            for (int nt = 0; nt < 8; ++nt) {
                atomicAdd(&shst[2 * nt], ls[nt]);
                atomicAdd(&shst[2 * nt + 1], lss[nt]);
            }
        }
        __syncthreads();
        if (tid < 16) atomicAdd(&g_stats[tid], shst[tid]);
    }
}

__global__ void fill_tail_kernel(float* out, long start, long end) {
    long i = start + (long)blockIdx.x * blockDim.x + threadIdx.x;
    if (i < end) out[i] = 0.f;
}

// ---------------------------------------------------------------------------
extern "C" void kernel_launch(void* const* d_in, const int* in_sizes, int n_in,
                              void* d_out, int out_size) {
    const float* x      = (const float*)d_in[0];
    const int*   nbr    = (const int*)d_in[1];
    const float* gamma1 = (const float*)d_in[2];
    const float* beta1  = (const float*)d_in[3];
    const float* W1     = (const float*)d_in[4];
    const float* gamma2 = (const float*)d_in[5];
    const float* beta2  = (const float*)d_in[6];
    const float* W2     = (const float*)d_in[7];
    const float* Wskip  = (const float*)d_in[8];
    const float* bskip  = (const float*)d_in[9];
    float* out = (float*)d_out;

    int n = in_sizes[0] / 32;
    int nblk_mma = (n + 255) / 256;

    __half *xf16p = nullptr, *h1p = nullptr, *skp = nullptr,
           *w1p = nullptr, *w2p = nullptr, *wsp = nullptr;
    float *b1p = nullptr, *b2p = nullptr;
    cudaGetSymbolAddress((void**)&xf16p, g_xf16);
    cudaGetSymbolAddress((void**)&h1p, g_h1f16);
    cudaGetSymbolAddress((void**)&skp, g_skipf16);
    cudaGetSymbolAddress((void**)&w1p, g_w1);
    cudaGetSymbolAddress((void**)&w2p, g_w2);
    cudaGetSymbolAddress((void**)&wsp, g_ws);
    cudaGetSymbolAddress((void**)&b1p, g_bias1);
    cudaGetSymbolAddress((void**)&b2p, g_bias2);

    const int IDXB = 28672;
    const int SMEM1 = 1024 + IDXB + 4 * (16384 + 4096);  // 111616
    const int SMEM2 = 1024 + IDXB + 2 * (32768 + 8192);  // 111616
    const int SMEMS = 1024 + 16384 + 4096;               // 21504
    cudaFuncSetAttribute(mma_conv_kernel<false>,
                         cudaFuncAttributeMaxDynamicSharedMemorySize, SMEM1);
    cudaFuncSetAttribute(mma_conv_kernel<true>,
                         cudaFuncAttributeMaxDynamicSharedMemorySize, SMEM2);

    // fused GN1 stats + x fp16 conversion (produces g_xf16 for skip too)
    zero_all_kernel<<<1, 160>>>();
    gn1_prep_kernel<<<1184, 256>>>(x, n);
    gn_finalize_kernel<32><<<1, 64>>>(gamma1, beta1, n);   // also re-zeros g_stats
    prepW1_kernel<<<KT, 64>>>(W1);
    prepWs_kernel<<<1, 64>>>(Wskip);

    // skip path -> g_skipf16 (fp16, tensor cores)
    skip_mma_kernel<<<nblk_mma, 256, SMEMS>>>(xf16p, wsp, bskip, n);

    // conv1 -> g_h1f16 (fp16, post-SiLU); epilogue accumulates GN2 stats
    mma_conv_kernel<false><<<nblk_mma, 256, SMEM1>>>(
        xf16p, nbr, w1p, b1p, nullptr, (void*)h1p, n);

    gn_finalize_kernel<64><<<1, 64>>>(gamma2, beta2, n);
    prepW2_kernel<<<KT, 64>>>(W2);

    // conv2 -> out = silu(conv2) + skip
    mma_conv_kernel<true><<<nblk_mma, 256, SMEM2>>>(
        h1p, nbr, w2p, b2p, skp, (void*)out, n);

    long main_elems = (long)n * 64;
    if ((long)out_size > main_elems) {
        long tail = (long)out_size - main_elems;
        int tb = (int)((tail + 255) / 256);
        fill_tail_kernel<<<tb, 256>>>(out, main_elems, (long)out_size);
    }
}

// round 15
// speedup vs baseline: 2.3118x; 1.0382x over previous
#include <cuda_runtime.h>
#include <cuda_fp16.h>
#include <math.h>
#include <stdint.h>

#define NMAX 500000
#define NGROUPS 8
#define KT 27

// ---------------------------------------------------------------------------
// Device global scratch (no allocation allowed in kernel_launch)
// ---------------------------------------------------------------------------
__device__ __half g_xf16[(size_t)NMAX * 32];    // activations conv1, fp16 rows 64B
__device__ __half g_h1f16[(size_t)NMAX * 64];   // conv1 output (post-SiLU), rows 128B
__device__ __half g_skipf16[(size_t)NMAX * 64]; // skip path (fp16)
__device__ __half g_w1[KT * 64 * 32];           // [k][n][c]
__device__ __half g_w2[KT * 64 * 64];           // [k][n][c]
__device__ __half g_ws[64 * 32];                // Wskip transposed [n][c]
__device__ float g_bias1[64];
__device__ float g_bias2[64];
__device__ float g_stats1[16];                  // GN1 accumulation
__device__ float g_stats2[16];                  // GN2 accumulation

// ---------------------------------------------------------------------------
// Helpers
// ---------------------------------------------------------------------------
__device__ __forceinline__ uint32_t smem_to_u32(const void* p) {
    uint32_t a;
    asm("{ .reg .u64 t; cvta.to.shared.u64 t, %1; cvt.u32.u64 %0, t; }" : "=r"(a) : "l"(p));
    return a;
}
__device__ __forceinline__ void cp16(uint32_t dst, const void* src) {
    asm volatile("cp.async.cg.shared.global [%0], [%1], 16;" :: "r"(dst), "l"(src));
}
#define CP_COMMIT() asm volatile("cp.async.commit_group;" ::: "memory")
#define CP_WAIT(N) asm volatile("cp.async.wait_group %0;" :: "n"(N) : "memory")

__device__ __forceinline__ void ldsm4(uint32_t* r, uint32_t addr) {
    asm volatile("ldmatrix.sync.aligned.m8n8.x4.shared.b16 {%0,%1,%2,%3}, [%4];"
                 : "=r"(r[0]), "=r"(r[1]), "=r"(r[2]), "=r"(r[3]) : "r"(addr));
}
__device__ __forceinline__ void ldsm2(uint32_t* r, uint32_t addr) {
    asm volatile("ldmatrix.sync.aligned.m8n8.x2.shared.b16 {%0,%1}, [%2];"
                 : "=r"(r[0]), "=r"(r[1]) : "r"(addr));
}
__device__ __forceinline__ void mma16816(float* d, const uint32_t* a, const uint32_t* b) {
    asm volatile(
        "mma.sync.aligned.m16n8k16.row.col.f32.f16.f16.f32 "
        "{%0,%1,%2,%3}, {%4,%5,%6,%7}, {%8,%9}, {%0,%1,%2,%3};"
        : "+f"(d[0]), "+f"(d[1]), "+f"(d[2]), "+f"(d[3])
        : "r"(a[0]), "r"(a[1]), "r"(a[2]), "r"(a[3]), "r"(b[0]), "r"(b[1]));
}
__device__ __forceinline__ float silu_f(float t) { return t / (1.f + __expf(-t)); }

// ---------------------------------------------------------------------------
// Zero kernel (both stats arrays + both bias accumulators, once)
// ---------------------------------------------------------------------------
__global__ void zero_all_kernel() {
    int t = threadIdx.x;
    if (t < 16) g_stats1[t] = 0.f;
    if (t >= 16 && t < 32) g_stats2[t - 16] = 0.f;
    if (t >= 32 && t < 96) g_bias1[t - 32] = 0.f;
    if (t >= 96 && t < 160) g_bias2[t - 96] = 0.f;
}

// ---------------------------------------------------------------------------
// Fused: GN1 stats + fp32->fp16 conversion of x (single read pass)
// ---------------------------------------------------------------------------
__global__ void gn1_prep_kernel(const float* __restrict__ x, int n) {
    int tid = blockIdx.x * blockDim.x + threadIdx.x;
    int total = gridDim.x * blockDim.x;     // multiple of 4
    int q = tid & 3;
    float s0 = 0.f, ss0 = 0.f, s1 = 0.f, ss1 = 0.f;
    long nQ = (long)n * 4;
    for (long e = tid; e < nQ; e += total) {
        long v = e >> 2;
        const float4* src = (const float4*)(x + v * 32 + q * 8);
        float4 a = src[0], b = src[1];
        uint32_t w[4];
        __half2 h;
        h = __floats2half2_rn(a.x, a.y); w[0] = *(uint32_t*)&h;
        h = __floats2half2_rn(a.z, a.w); w[1] = *(uint32_t*)&h;
        h = __floats2half2_rn(b.x, b.y); w[2] = *(uint32_t*)&h;
        h = __floats2half2_rn(b.z, b.w); w[3] = *(uint32_t*)&h;
        *(uint4*)(g_xf16 + v * 32 + q * 8) = *(uint4*)w;
        s0 += (a.x + a.y) + (a.z + a.w);
        ss0 += a.x * a.x + a.y * a.y + a.z * a.z + a.w * a.w;
        s1 += (b.x + b.y) + (b.z + b.w);
        ss1 += b.x * b.x + b.y * b.y + b.z * b.z + b.w * b.w;
    }
    __shared__ float sh[16];
    if (threadIdx.x < 16) sh[threadIdx.x] = 0.f;
    __syncthreads();
    atomicAdd(&sh[4 * q + 0], s0);
    atomicAdd(&sh[4 * q + 1], ss0);
    atomicAdd(&sh[4 * q + 2], s1);
    atomicAdd(&sh[4 * q + 3], ss1);
    __syncthreads();
    if (threadIdx.x < 16) atomicAdd(&g_stats1[threadIdx.x], sh[threadIdx.x]);
}

// ---------------------------------------------------------------------------
// Weight prep with inline GN finalize (each block recomputes scale/bias
// locally from the stats array — tiny redundant math, no extra launch).
// prepW1: grid KT+1; block KT handles the Wskip transpose instead.
// 256 threads: tid = q*64 + nn, q-th group handles channel range.
// ---------------------------------------------------------------------------
__global__ void __launch_bounds__(256)
prepW1_kernel(const float* __restrict__ W1,
              const float* __restrict__ Wskip,
              const float* __restrict__ gamma,
              const float* __restrict__ beta, int n) {
    const int k = blockIdx.x;
    const int tid = threadIdx.x;
    const int nn = tid & 63;
    const int q = tid >> 6;

    if (k == KT) {   // Wskip [32][64] -> g_ws [n][c] fp16
        for (int c = q * 8; c < q * 8 + 8; ++c)
            g_ws[nn * 32 + c] = __float2half_rn(Wskip[(size_t)c * 64 + nn]);
        return;
    }

    __shared__ float ssc[32], sbi[32];
    if (tid < 32) {
        int c = tid;
        int g = c / 4;                      // 32 ch / 8 groups
        float cnt = (float)n * 4;
        float mean = g_stats1[2 * g] / cnt;
        float var = g_stats1[2 * g + 1] / cnt - mean * mean;
        float sc = gamma[c] * rsqrtf(var + 1e-5f);
        ssc[c] = sc;
        sbi[c] = beta[c] - mean * sc;
    }
    __syncthreads();

    float bs = 0.f;
    for (int c = q * 8; c < q * 8 + 8; ++c) {
        float w = W1[((size_t)(k * 32 + c)) * 64 + nn];
        bs += sbi[c] * w;
        g_w1[((size_t)(k * 64 + nn)) * 32 + c] = __float2half_rn(w * ssc[c]);
    }
    atomicAdd(&g_bias1[nn], bs);
}

__global__ void __launch_bounds__(256)
prepW2_kernel(const float* __restrict__ W2,
              const float* __restrict__ gamma,
              const float* __restrict__ beta, int n) {
    const int k = blockIdx.x;
    const int tid = threadIdx.x;
    const int nn = tid & 63;
    const int q = tid >> 6;

    __shared__ float ssc[64], sbi[64];
    if (tid < 64) {
        int c = tid;
        int g = c / 8;                      // 64 ch / 8 groups
        float cnt = (float)n * 8;
        float mean = g_stats2[2 * g] / cnt;
        float var = g_stats2[2 * g + 1] / cnt - mean * mean;
        float sc = gamma[c] * rsqrtf(var + 1e-5f);
        ssc[c] = sc;
        sbi[c] = beta[c] - mean * sc;
    }
    __syncthreads();

    float bs = 0.f;
    for (int c = q * 16; c < q * 16 + 16; ++c) {
        float w = W2[((size_t)(k * 64 + c)) * 64 + nn];
        bs += sbi[c] * w;
        g_w2[((size_t)(k * 64 + nn)) * 64 + c] = __float2half_rn(w * ssc[c]);
    }
    atomicAdd(&g_bias2[nn], bs);
}

// ---------------------------------------------------------------------------
// Skip path via MMA: g_skipf16[v] = fp16(xf16[v] @ Ws + bskip)
// One CTA = 256 voxels, 8 warps m32 x n64, single stage (contiguous rows).
// ---------------------------------------------------------------------------
__global__ void __launch_bounds__(256, 2)
skip_mma_kernel(const __half* __restrict__ Araw,   // g_xf16
                const __half* __restrict__ Bw,     // g_ws
                const float* __restrict__ obias,   // bskip
                int n) {
    extern __shared__ __align__(1024) char dsmem[];
    float* sbias = (float*)dsmem;
    const uint32_t Ab = smem_to_u32(dsmem + 1024);
    const uint32_t Bb = Ab + 16384u;

    const int tid = threadIdx.x;
    const int w = tid >> 5;
    const int lane = tid & 31;
    const int v0 = blockIdx.x * 256;
    const int lastrow = n - 1 - v0;

    if (tid < 64) sbias[tid] = obias[tid];

    // stage A (contiguous 256 rows x 64B) + B (64 rows x 64B)
    {
        const int lrow = tid >> 2, lchk = tid & 3;
#pragma unroll
        for (int p = 0; p < 4; ++p) {
            int row = p * 64 + lrow;
            int vr = row < lastrow ? row : lastrow;
            cp16(Ab + (uint32_t)row * 64 +
                     (((uint32_t)lchk ^ ((uint32_t)row & 3)) << 4),
                 (const char*)Araw + ((size_t)(v0 + vr) * 32 + lchk * 8) * 2);
        }
        {
            int q = tid;                          // 256 chunks
            int row = q >> 2;
            uint32_t c = (uint32_t)(q & 3);
            cp16(Bb + (uint32_t)row * 64 + ((c ^ ((uint32_t)row & 3)) << 4),
                 (const char*)Bw + (size_t)q * 16);
        }
        CP_COMMIT();
        CP_WAIT(0);
        __syncthreads();
    }

    const uint32_t asel = (uint32_t)(lane >> 4);
    const int brow = lane & 7;
    const uint32_t bsel = (uint32_t)((lane >> 3) & 1);
    const int arow0 = w * 32 + (lane & 15);

    float acc[2][8][4];
#pragma unroll
    for (int s = 0; s < 2; ++s)
#pragma unroll
        for (int i = 0; i < 8; ++i)
#pragma unroll
            for (int j = 0; j < 4; ++j) acc[s][i][j] = 0.f;

    uint32_t a[2][2][4];
#pragma unroll
    for (int s = 0; s < 2; ++s) {
        const int ar = arow0 + s * 16;
#pragma unroll
        for (int kc = 0; kc < 2; ++kc)
            ldsm4(a[s][kc], Ab + (uint32_t)ar * 64 +
                            ((((uint32_t)kc * 2 + asel) ^ ((uint32_t)ar & 3)) << 4));
    }
#pragma unroll
    for (int nt = 0; nt < 8; ++nt) {
#pragma unroll
        for (int kc = 0; kc < 2; ++kc) {
            uint32_t b2[2];
            ldsm2(b2, Bb + (uint32_t)nt * 512 + (uint32_t)brow * 64 +
                          ((((uint32_t)kc * 2 + bsel) ^ ((uint32_t)brow & 3)) << 4));
            mma16816(acc[0][nt], a[0][kc], b2);
            mma16816(acc[1][nt], a[1][kc], b2);
        }
    }

    const int g = lane >> 2, tg = lane & 3;
#pragma unroll
    for (int s = 0; s < 2; ++s) {
        const int row0 = v0 + w * 32 + s * 16 + g;
#pragma unroll
        for (int half = 0; half < 2; ++half) {
            int v = row0 + half * 8;
            if (v < n) {
                __half* po = g_skipf16 + (size_t)v * 64;
#pragma unroll
                for (int nt = 0; nt < 8; ++nt) {
                    int c = nt * 8 + tg * 2;
                    __half2 hh = __floats2half2_rn(
                        acc[s][nt][half * 2 + 0] + sbias[c],
                        acc[s][nt][half * 2 + 1] + sbias[c + 1]);
                    *(uint32_t*)(po + c) = *(uint32_t*)&hh;
                }
            }
        }
    }
}

// ---------------------------------------------------------------------------
// mma.sync gather-conv (proven R13/R14): fp16 x fp16, SMEM index block staged
// straight from nbr [v][k]; warp m32 x n64.
// CONV2=false: CIN=32, 4-stage distance-2; out fp16; GN2 stats in epilogue.
// CONV2=true : CIN=64, 2-stage; out fp32 = silu(conv)+skip.
// ---------------------------------------------------------------------------
template <bool CONV2>
__global__ void __launch_bounds__(256, 2)
mma_conv_kernel(const __half* __restrict__ Araw,
                const int* __restrict__ nbr,    // original [v][KT]
                const __half* __restrict__ Bw,
                const float* __restrict__ biasv,
                const __half* __restrict__ skipf,  // conv2 only
                void* __restrict__ outp, int n) {
    constexpr uint32_t IDX_BYTES = 28672u;                 // >= 1729*16, padded
    constexpr uint32_t A_BYTES = CONV2 ? 32768u : 16384u;  // 256 rows
    constexpr uint32_t B_BYTES = CONV2 ? 8192u : 4096u;    // 64 rows
    constexpr uint32_t STRIDE = A_BYTES + B_BYTES;
    constexpr int NSTAGE = CONV2 ? 2 : 4;
    constexpr int NCHUNK = (256 * KT) / 4 + 1;             // 1729

    extern __shared__ __align__(1024) char dsmem[];
    float* sbias = (float*)dsmem;
    float* shst = (float*)(dsmem + 512);     // GN2 stats staging (16 floats)
    int* sidxw = (int*)(dsmem + 1024);
    const uint32_t idxb = smem_to_u32(dsmem + 1024);
    const uint32_t base0 = idxb + IDX_BYTES;

    const int tid = threadIdx.x;
    const int w = tid >> 5;
    const int lane = tid & 31;
    const int v0 = blockIdx.x * 256;
    const int lastrow = n - 1 - v0;          // >= 0; >= 255 for full CTAs

    if (tid < 64) sbias[tid] = biasv[tid];
    if constexpr (!CONV2) {
        if (tid < 16) shst[tid] = 0.f;
    }

    // ---- stage index block straight from nbr (contiguous in [v][k]) ----
    const int base_int = (v0 * KT) & ~3;     // 16B-aligned start
    const int ofs = v0 * KT - base_int;      // 0..3
    {
        const int total_ints = n * KT;
#pragma unroll
        for (int j = 0; j < 7; ++j) {
            int c = tid + j * 256;
            if (c < NCHUNK) {
                int gi = base_int + c * 4;
                if (gi + 4 <= total_ints) {
                    cp16(idxb + (uint32_t)c * 16, nbr + gi);
                } else {
#pragma unroll
                    for (int t = 0; t < 4; ++t) {
                        int g2 = gi + t;
                        sidxw[c * 4 + t] = (g2 < total_ints) ? nbr[g2] : 0;
                    }
                }
            }
        }
        CP_COMMIT();
        CP_WAIT(0);
        __syncthreads();
    }
    const int* si = sidxw + ofs;

    // fragment address components
    const uint32_t asel = (uint32_t)(lane >> 4);        // k-chunk low/high 8
    const int brow = lane & 7;
    const uint32_t bsel = (uint32_t)((lane >> 3) & 1);
    const int arow0 = w * 32 + (lane & 15);             // slab 0 row; slab1 = +16

    float acc[2][8][4];
#pragma unroll
    for (int s = 0; s < 2; ++s)
#pragma unroll
        for (int i = 0; i < 8; ++i)
#pragma unroll
            for (int j = 0; j < 4; ++j) acc[s][i][j] = 0.f;

    // stage loader: consecutive lanes cover one row's 16B chunks;
    // index = si[min(row, lastrow)*KT + k] (tail clamped)
    auto load_tap = [&](int k, uint32_t stage) {
        if constexpr (CONV2) {
            const int lrow = tid >> 3, lchk = tid & 7;   // 32 rows/pass, 8 passes
#pragma unroll
            for (int p = 0; p < 8; ++p) {
                int row = p * 32 + lrow;
                int vr = row < lastrow ? row : lastrow;
                int idx = si[vr * KT + k];
                cp16(stage + (uint32_t)row * 128 +
                         (((uint32_t)lchk ^ ((uint32_t)row & 7)) << 4),
                     (const char*)Araw + (size_t)idx * 128 + lchk * 16);
            }
#pragma unroll
            for (int j = 0; j < 2; ++j) {
                int q = tid + j * 256;               // 512 chunks of 16B
                int row = q >> 3;
                uint32_t c = (uint32_t)(q & 7);
                cp16(stage + A_BYTES + (uint32_t)row * 128 +
                         ((c ^ ((uint32_t)row & 7)) << 4),
                     (const char*)Bw + (size_t)k * 8192 + (size_t)q * 16);
            }
        } else {
            const int lrow = tid >> 2, lchk = tid & 3;   // 64 rows/pass, 4 passes
#pragma unroll
            for (int p = 0; p < 4; ++p) {
                int row = p * 64 + lrow;
                int vr = row < lastrow ? row : lastrow;
                int idx = si[vr * KT + k];
                cp16(stage + (uint32_t)row * 64 +
                         (((uint32_t)lchk ^ ((uint32_t)row & 3)) << 4),
                     (const char*)Araw + (size_t)idx * 64 + lchk * 16);
            }
            {
                int q = tid;                          // 256 chunks of 16B
                int row = q >> 2;
                uint32_t c = (uint32_t)(q & 3);
                cp16(stage + A_BYTES + (uint32_t)row * 64 +
                         ((c ^ ((uint32_t)row & 3)) << 4),
                     (const char*)Bw + (size_t)k * 4096 + (size_t)q * 16);
            }
        }
    };

    // prologue
    if constexpr (CONV2) {
        load_tap(0, base0);
        CP_COMMIT();
    } else {
        load_tap(0, base0);
        CP_COMMIT();
        load_tap(1, base0 + STRIDE);
        CP_COMMIT();
    }

    for (int k = 0; k < KT; ++k) {
        if constexpr (CONV2) {
            __syncthreads();
            if (k + 1 < KT) {
                load_tap(k + 1, base0 + (uint32_t)((k + 1) & 1) * STRIDE);
                CP_COMMIT();
                CP_WAIT(1);
            } else {
                CP_WAIT(0);
            }
            __syncthreads();
        } else {
            if (k + 2 < KT) {
                load_tap(k + 2, base0 + (uint32_t)((k + 2) & 3) * STRIDE);
                CP_COMMIT();
                CP_WAIT(2);
            } else if (k + 1 < KT) {
                CP_WAIT(1);
            } else {
                CP_WAIT(0);
            }
            __syncthreads();
        }
        const uint32_t Ab = base0 + (uint32_t)(k % NSTAGE) * STRIDE;
        const uint32_t Bb = Ab + A_BYTES;
        if constexpr (CONV2) {
            uint32_t a[2][4][4];
#pragma unroll
            for (int s = 0; s < 2; ++s) {
                const int ar = arow0 + s * 16;
#pragma unroll
                for (int kc = 0; kc < 4; ++kc)
                    ldsm4(a[s][kc], Ab + (uint32_t)ar * 128 +
                                    ((((uint32_t)kc * 2 + asel) ^ ((uint32_t)ar & 7)) << 4));
            }
#pragma unroll
            for (int nt = 0; nt < 8; ++nt) {
#pragma unroll
                for (int kc = 0; kc < 4; ++kc) {
                    uint32_t b2[2];
                    ldsm2(b2, Bb + (uint32_t)nt * 1024 + (uint32_t)brow * 128 +
                                  ((((uint32_t)kc * 2 + bsel) ^ ((uint32_t)brow & 7)) << 4));
                    mma16816(acc[0][nt], a[0][kc], b2);
                    mma16816(acc[1][nt], a[1][kc], b2);
                }
            }
        } else {
            uint32_t a[2][2][4];
#pragma unroll
            for (int s = 0; s < 2; ++s) {
                const int ar = arow0 + s * 16;
#pragma unroll
                for (int kc = 0; kc < 2; ++kc)
                    ldsm4(a[s][kc], Ab + (uint32_t)ar * 64 +
                                    ((((uint32_t)kc * 2 + asel) ^ ((uint32_t)ar & 3)) << 4));
            }
#pragma unroll
            for (int nt = 0; nt < 8; ++nt) {
#pragma unroll
                for (int kc = 0; kc < 2; ++kc) {
                    uint32_t b2[2];
                    ldsm2(b2, Bb + (uint32_t)nt * 512 + (uint32_t)brow * 64 +
                                  ((((uint32_t)kc * 2 + bsel) ^ ((uint32_t)brow & 3)) << 4));
                    mma16816(acc[0][nt], a[0][kc], b2);
                    mma16816(acc[1][nt], a[1][kc], b2);
                }
            }
        }
    }

    // ---- epilogue ----
    const int g = lane >> 2, tg = lane & 3;
    float ls[8], lss[8];
    if constexpr (!CONV2) {
#pragma unroll
        for (int nt = 0; nt < 8; ++nt) { ls[nt] = 0.f; lss[nt] = 0.f; }
    }
#pragma unroll
    for (int s = 0; s < 2; ++s) {
        const int row0 = v0 + w * 32 + s * 16 + g;
#pragma unroll
        for (int half = 0; half < 2; ++half) {
            int v = row0 + half * 8;
            if (v < n) {
                if constexpr (CONV2) {
                    float* po = (float*)outp + (size_t)v * 64;
                    const __half* sk = skipf + (size_t)v * 64;
#pragma unroll
                    for (int nt = 0; nt < 8; ++nt) {
                        int c = nt * 8 + tg * 2;
                        __half2 s2 = *(const __half2*)(sk + c);
                        float2 skf = __half22float2(s2);
                        float2 rr;
                        rr.x = silu_f(acc[s][nt][half * 2 + 0] + sbias[c]) + skf.x;
                        rr.y = silu_f(acc[s][nt][half * 2 + 1] + sbias[c + 1]) + skf.y;
                        *(float2*)(po + c) = rr;
                    }
                } else {
                    char* basep = (char*)outp + (size_t)v * 128;
#pragma unroll
                    for (int nt = 0; nt < 8; ++nt) {
                        int c = nt * 8 + tg * 2;
                        float f0 = silu_f(acc[s][nt][half * 2 + 0] + sbias[c]);
                        float f1 = silu_f(acc[s][nt][half * 2 + 1] + sbias[c + 1]);
                        __half2 hh = __floats2half2_rn(f0, f1);
                        *(uint32_t*)(basep + c * 2) = *(uint32_t*)&hh;
                        ls[nt] += f0 + f1;
                        lss[nt] += f0 * f0 + f1 * f1;
                    }
                }
            }
        }
    }
    if constexpr (!CONV2) {
#pragma unroll
        for (int nt = 0; nt < 8; ++nt) {
#pragma unroll
            for (int o = 16; o > 0; o >>= 1) {
                ls[nt] += __shfl_xor_sync(0xFFFFFFFFu, ls[nt], o);
                lss[nt] += __shfl_xor_sync(0xFFFFFFFFu, lss[nt], o);
            }
        }
        if (lane == 0) {
#pragma unroll
            for (int nt = 0; nt < 8; ++nt) {
                atomicAdd(&shst[2 * nt], ls[nt]);
                atomicAdd(&shst[2 * nt + 1], lss[nt]);
            }
        }
        __syncthreads();
        if (tid < 16) atomicAdd(&g_stats2[tid], shst[tid]);
    }
}

__global__ void fill_tail_kernel(float* out, long start, long end) {
    long i = start + (long)blockIdx.x * blockDim.x + threadIdx.x;
    if (i < end) out[i] = 0.f;
}

// ---------------------------------------------------------------------------
extern "C" void kernel_launch(void* const* d_in, const int* in_sizes, int n_in,
                              void* d_out, int out_size) {
    const float* x      = (const float*)d_in[0];
    const int*   nbr    = (const int*)d_in[1];
    const float* gamma1 = (const float*)d_in[2];
    const float* beta1  = (const float*)d_in[3];
    const float* W1     = (const float*)d_in[4];
    const float* gamma2 = (const float*)d_in[5];
    const float* beta2  = (const float*)d_in[6];
    const float* W2     = (const float*)d_in[7];
    const float* Wskip  = (const float*)d_in[8];
    const float* bskip  = (const float*)d_in[9];
    float* out = (float*)d_out;

    int n = in_sizes[0] / 32;
    int nblk_mma = (n + 255) / 256;

    __half *xf16p = nullptr, *h1p = nullptr, *skp = nullptr,
           *w1p = nullptr, *w2p = nullptr, *wsp = nullptr;
    float *b1p = nullptr, *b2p = nullptr;
    cudaGetSymbolAddress((void**)&xf16p, g_xf16);
    cudaGetSymbolAddress((void**)&h1p, g_h1f16);
    cudaGetSymbolAddress((void**)&skp, g_skipf16);
    cudaGetSymbolAddress((void**)&w1p, g_w1);
    cudaGetSymbolAddress((void**)&w2p, g_w2);
    cudaGetSymbolAddress((void**)&wsp, g_ws);
    cudaGetSymbolAddress((void**)&b1p, g_bias1);
    cudaGetSymbolAddress((void**)&b2p, g_bias2);

    const int IDXB = 28672;
    const int SMEM1 = 1024 + IDXB + 4 * (16384 + 4096);  // 111616
    const int SMEM2 = 1024 + IDXB + 2 * (32768 + 8192);  // 111616
    const int SMEMS = 1024 + 16384 + 4096;               // 21504
    cudaFuncSetAttribute(mma_conv_kernel<false>,
                         cudaFuncAttributeMaxDynamicSharedMemorySize, SMEM1);
    cudaFuncSetAttribute(mma_conv_kernel<true>,
                         cudaFuncAttributeMaxDynamicSharedMemorySize, SMEM2);

    // fused GN1 stats + x fp16 conversion (produces g_xf16 for skip too)
    zero_all_kernel<<<1, 160>>>();
    gn1_prep_kernel<<<1184, 256>>>(x, n);
    // W1 prep (inline GN1 finalize) + Wskip transpose (extra block)
    prepW1_kernel<<<KT + 1, 256>>>(W1, Wskip, gamma1, beta1, n);

    // skip path -> g_skipf16 (fp16, tensor cores)
    skip_mma_kernel<<<nblk_mma, 256, SMEMS>>>(xf16p, wsp, bskip, n);

    // conv1 -> g_h1f16 (fp16, post-SiLU); epilogue accumulates GN2 stats
    mma_conv_kernel<false><<<nblk_mma, 256, SMEM1>>>(
        xf16p, nbr, w1p, b1p, nullptr, (void*)h1p, n);

    // W2 prep (inline GN2 finalize)
    prepW2_kernel<<<KT, 256>>>(W2, gamma2, beta2, n);

    // conv2 -> out = silu(conv2) + skip
    mma_conv_kernel<true><<<nblk_mma, 256, SMEM2>>>(
        h1p, nbr, w2p, b2p, skp, (void*)out, n);

    long main_elems = (long)n * 64;
    if ((long)out_size > main_elems) {
        long tail = (long)out_size - main_elems;
        int tb = (int)((tail + 255) / 256);
        fill_tail_kernel<<<tb, 256>>>(out, main_elems, (long)out_size);
    }
}